// round 7
// baseline (speedup 1.0000x reference)
#include <cuda_runtime.h>
#include <cuda_fp16.h>
#include <math.h>
#include <stdint.h>

#define NU 100000
#define NI 50000
#define KN 100
#define BB 8192

// Precomputed fp16 tables (scr padded to 104: cols 100-103 zero)
__device__ __half g_pe_user[NU * 64];
__device__ __half g_pe_item[NI * 64];
__device__ __half g_uscr16[(size_t)NU * 104];
__device__ __half g_iscr16[(size_t)NI * 104];
__device__ __half g_w2h[64 * 64];
__device__ __half g_w3h[32 * 64];
__device__ __half g_w4h[32 * 32];
__device__ __half g_b1h[64];
__device__ __half g_b2h[64];
__device__ __half g_b3h[32];
__device__ __half g_b4h[32];

// ---------------------------------------------------------------------------
// Main-kernel SMEM (byte offsets):
//   A1 [112 r][216 k-halves] stride 432B @ 0      (48384)  u cols 0-103, i 104-207
//   B1 [208 k][72 n] stride 144B         @ 48384  (29952)  rows 100-103,204-207 zero
//   W2 [64][72h]  stride 144             @ 78336  (9216)
//   W3 [32][72h]  stride 144             @ 87552  (4608)
//   W4 [32][40h]  stride 80              @ 92160  (2560)
//   MISC (floats)                        @ 94720  (1344)
// Total 96064 B -> 2 CTAs/SM
// ---------------------------------------------------------------------------
#define OFF_A1   0
#define OFF_B1   48384
#define OFF_W2   78336
#define OFF_W3   87552
#define OFF_W4   92160
#define OFF_MISC 94720
#define SMEM_BYTES 96064
// MISC float indices
#define MISC_W5   0
#define MISC_B5   32
#define MISC_RED  33
#define MISC_NIDX 136

#define CP_ASYNC16(dst, src) \
    asm volatile("cp.async.cg.shared.global [%0], [%1], 16;" :: "r"(dst), "l"(src))
#define CP_COMMIT() asm volatile("cp.async.commit_group;" ::: "memory")
#define CP_WAIT0()  asm volatile("cp.async.wait_group 0;" ::: "memory")

__device__ __forceinline__ void ldsm4(uint32_t (&r)[4], uint32_t a) {
    asm volatile("ldmatrix.sync.aligned.m8n8.x4.shared.b16 {%0,%1,%2,%3}, [%4];"
                 : "=r"(r[0]), "=r"(r[1]), "=r"(r[2]), "=r"(r[3]) : "r"(a));
}
__device__ __forceinline__ void ldsm2(uint32_t (&r)[2], uint32_t a) {
    asm volatile("ldmatrix.sync.aligned.m8n8.x2.shared.b16 {%0,%1}, [%2];"
                 : "=r"(r[0]), "=r"(r[1]) : "r"(a));
}
__device__ __forceinline__ void ldsm2t(uint32_t (&r)[2], uint32_t a) {
    asm volatile("ldmatrix.sync.aligned.m8n8.x2.trans.shared.b16 {%0,%1}, [%2];"
                 : "=r"(r[0]), "=r"(r[1]) : "r"(a));
}
__device__ __forceinline__ void mma_f32acc(float (&c)[4], const uint32_t (&a)[4],
                                           const uint32_t (&b)[2]) {
    asm volatile(
        "mma.sync.aligned.m16n8k16.row.col.f32.f16.f16.f32 "
        "{%0,%1,%2,%3}, {%4,%5,%6,%7}, {%8,%9}, {%0,%1,%2,%3};"
        : "+f"(c[0]), "+f"(c[1]), "+f"(c[2]), "+f"(c[3])
        : "r"(a[0]), "r"(a[1]), "r"(a[2]), "r"(a[3]), "r"(b[0]), "r"(b[1]));
}
__device__ __forceinline__ void mma_f16acc(uint32_t (&c)[2], const uint32_t (&a)[4],
                                           const uint32_t (&b)[2]) {
    asm volatile(
        "mma.sync.aligned.m16n8k16.row.col.f16.f16.f16.f16 "
        "{%0,%1}, {%2,%3,%4,%5}, {%6,%7}, {%0,%1};"
        : "+r"(c[0]), "+r"(c[1])
        : "r"(a[0]), "r"(a[1]), "r"(a[2]), "r"(a[3]), "r"(b[0]), "r"(b[1]));
}

__device__ __forceinline__ uint32_t h2_bits(float x, float y) {
    __half2 h = __floats2half2_rn(x, y);
    return *(uint32_t*)&h;
}
__device__ __forceinline__ void cvt_store4(char* dst, float4 v) {
    uint32_t lo = h2_bits(v.x, v.y), hi = h2_bits(v.z, v.w);
    uint2 u; u.x = lo; u.y = hi;
    *(uint2*)dst = u;
}

// ---------------------------------------------------------------------------
// pe_kernel (tensor core): 256 rows/block, each warp 2 m16 tiles.
// ---------------------------------------------------------------------------
__global__ __launch_bounds__(256) void pe_kernel(
    const float* __restrict__ emb, const float* __restrict__ w1,
    int w1_off, int which, int nrows)
{
    __shared__ __half W1h[64 * 72];
    __shared__ __half E[256 * 72];
    __half* __restrict__ pe = which ? g_pe_item : g_pe_user;

    const int tid = threadIdx.x;
    const int rows0 = blockIdx.x * 256;

    for (int t = tid; t < 64 * 16; t += 256) {
        int o = t >> 4, k4 = t & 15;
        float4 v = *(const float4*)(w1 + o * 128 + w1_off + k4 * 4);
        cvt_store4((char*)(W1h + o * 72 + k4 * 4), v);
    }
    for (int t = tid; t < 256 * 16; t += 256) {
        int r = t >> 4, k4 = t & 15;
        int n = rows0 + r;
        float4 v = (n < nrows) ? *(const float4*)(emb + (size_t)n * 64 + k4 * 4)
                               : make_float4(0.f, 0.f, 0.f, 0.f);
        cvt_store4((char*)(E + r * 72 + k4 * 4), v);
    }
    __syncthreads();

    const int lane = tid & 31, w = tid >> 5;
    uint32_t sE = (uint32_t)__cvta_generic_to_shared(E);
    uint32_t sW = (uint32_t)__cvta_generic_to_shared(W1h);
    uint32_t aAddr[2];
#pragma unroll
    for (int mt = 0; mt < 2; mt++)
        aAddr[mt] = sE + (uint32_t)(w * 32 + mt * 16 + (lane & 15)) * 144u
                  + (uint32_t)((lane >> 4) << 4);
    uint32_t bAddr0 = sW + (uint32_t)(lane & 7) * 144u + (uint32_t)(((lane >> 3) & 1) << 4);

    float acc[2][8][4];
#pragma unroll
    for (int mt = 0; mt < 2; mt++)
#pragma unroll
        for (int nt = 0; nt < 8; nt++)
#pragma unroll
            for (int i = 0; i < 4; i++) acc[mt][nt][i] = 0.f;

#pragma unroll
    for (int ks = 0; ks < 4; ks++) {
        uint32_t a[2][4];
        ldsm4(a[0], aAddr[0] + ks * 32);
        ldsm4(a[1], aAddr[1] + ks * 32);
#pragma unroll
        for (int nt = 0; nt < 8; nt++) {
            uint32_t b[2];
            ldsm2(b, bAddr0 + (uint32_t)nt * 8u * 144u + ks * 32);
            mma_f32acc(acc[0][nt], a[0], b);
            mma_f32acc(acc[1][nt], a[1], b);
        }
    }

    int c0 = (lane & 3) * 2;
#pragma unroll
    for (int mt = 0; mt < 2; mt++) {
        int r0 = rows0 + w * 32 + mt * 16 + (lane >> 2);
#pragma unroll
        for (int nt = 0; nt < 8; nt++) {
            int col = nt * 8 + c0;
            if (r0 < nrows)
                *(__half2*)(pe + (size_t)r0 * 64 + col) =
                    __floats2half2_rn(acc[mt][nt][0], acc[mt][nt][1]);
            if (r0 + 8 < nrows)
                *(__half2*)(pe + (size_t)(r0 + 8) * 64 + col) =
                    __floats2half2_rn(acc[mt][nt][2], acc[mt][nt][3]);
        }
    }
}

// ---------------------------------------------------------------------------
// scr_cvt: fp32 scr [nrows][100] -> fp16 padded [nrows][104] (cols 100-103 = 0)
// ---------------------------------------------------------------------------
__global__ __launch_bounds__(256) void scr_cvt_kernel(
    const float* __restrict__ src, int which, int nrows)
{
    __half* __restrict__ dst = which ? g_iscr16 : g_uscr16;
    int total = nrows * 13;
    for (int t = blockIdx.x * 256 + threadIdx.x; t < total; t += gridDim.x * 256) {
        int n = t / 13, cb = t % 13;
        uint32_t o[4];
        if (cb < 12) {
            float4 a = *(const float4*)(src + (size_t)n * 100 + cb * 8);
            float4 bq = *(const float4*)(src + (size_t)n * 100 + cb * 8 + 4);
            o[0] = h2_bits(a.x, a.y);  o[1] = h2_bits(a.z, a.w);
            o[2] = h2_bits(bq.x, bq.y); o[3] = h2_bits(bq.z, bq.w);
        } else {
            float4 a = *(const float4*)(src + (size_t)n * 100 + 96);
            o[0] = h2_bits(a.x, a.y);  o[1] = h2_bits(a.z, a.w);
            o[2] = 0u; o[3] = 0u;
        }
        uint4 v; v.x = o[0]; v.y = o[1]; v.z = o[2]; v.w = o[3];
        *(uint4*)(dst + (size_t)n * 104 + cb * 8) = v;
    }
}

__global__ __launch_bounds__(256) void wcvt_kernel(
    const float* __restrict__ w2, const float* __restrict__ w3,
    const float* __restrict__ w4, const float* __restrict__ b1,
    const float* __restrict__ b2, const float* __restrict__ b3,
    const float* __restrict__ b4)
{
    int t = blockIdx.x * 256 + threadIdx.x;
    if (t < 4096) g_w2h[t] = __float2half_rn(w2[t]);
    else if (t < 6144) g_w3h[t - 4096] = __float2half_rn(w3[t - 4096]);
    else if (t < 7168) g_w4h[t - 6144] = __float2half_rn(w4[t - 6144]);
    else if (t < 7232) g_b1h[t - 7168] = __float2half_rn(b1[t - 7168]);
    else if (t < 7296) g_b2h[t - 7232] = __float2half_rn(b2[t - 7232]);
    else if (t < 7328) g_b3h[t - 7296] = __float2half_rn(b3[t - 7296]);
    else if (t < 7360) g_b4h[t - 7328] = __float2half_rn(b4[t - 7328]);
}

// ---------------------------------------------------------------------------
// Block-cooperative f16-acc MLP layer (round-5 structure):
// A [112][K] row-major, B weights [N][K] n-major, C = relu(A@B^T + bias) fp16.
// Warp w: mw=w>>1 (2 m-tiles, mw==3 -> 1), nw=w&1 (NT n-tiles).
// ---------------------------------------------------------------------------
template <int KS, int NT, int ASTR, int BSTR, int CSTR>
__device__ __forceinline__ void layer_f16(
    uint32_t sbase, int aOff, int bOff, int cOff,
    const __half* __restrict__ bias, char* __restrict__ smb)
{
    const int lane = threadIdx.x & 31;
    const int w = threadIdx.x >> 5;
    const int mw = w >> 1, nw = w & 1;
    const int mtn = (mw == 3) ? 1 : 2;
    const int cc = (lane & 3) * 2;

    __half2 bias2[NT];
#pragma unroll
    for (int nt = 0; nt < NT; nt++)
        bias2[nt] = *(const __half2*)(bias + nw * NT * 8 + nt * 8 + cc);

    uint32_t aAddr[2];
#pragma unroll
    for (int mt = 0; mt < 2; mt++)
        aAddr[mt] = sbase + (uint32_t)aOff
                  + (uint32_t)(mw * 32 + mt * 16 + (lane & 15)) * ASTR
                  + (uint32_t)((lane >> 4) << 4);
    uint32_t bAddr[NT];
#pragma unroll
    for (int nt = 0; nt < NT; nt++)
        bAddr[nt] = sbase + (uint32_t)bOff
                  + (uint32_t)(nw * NT * 8 + nt * 8 + (lane & 7)) * BSTR
                  + (uint32_t)(((lane >> 3) & 1) << 4);

    uint32_t acc[2][NT][2];
#pragma unroll
    for (int mt = 0; mt < 2; mt++)
#pragma unroll
        for (int nt = 0; nt < NT; nt++) { acc[mt][nt][0] = 0u; acc[mt][nt][1] = 0u; }

#pragma unroll
    for (int ks = 0; ks < KS; ks++) {
        uint32_t b[NT][2];
#pragma unroll
        for (int nt = 0; nt < NT; nt++) ldsm2(b[nt], bAddr[nt] + ks * 32);
#pragma unroll
        for (int mt = 0; mt < 2; mt++) {
            if (mt < mtn) {
                uint32_t a[4];
                ldsm4(a, aAddr[mt] + ks * 32);
#pragma unroll
                for (int nt = 0; nt < NT; nt++) mma_f16acc(acc[mt][nt], a, b[nt]);
            }
        }
    }

    const int r = lane >> 2;
    const __half2 z = __floats2half2_rn(0.f, 0.f);
#pragma unroll
    for (int mt = 0; mt < 2; mt++) {
        if (mt < mtn) {
            int row = mw * 32 + mt * 16 + r;
#pragma unroll
            for (int nt = 0; nt < NT; nt++) {
                int col = nw * NT * 8 + nt * 8 + cc;
                __half2 v0 = __hmax2(__hadd2(*(__half2*)&acc[mt][nt][0], bias2[nt]), z);
                __half2 v1 = __hmax2(__hadd2(*(__half2*)&acc[mt][nt][1], bias2[nt]), z);
                *(uint32_t*)(smb + cOff + row * CSTR + col * 2) = *(uint32_t*)&v0;
                *(uint32_t*)(smb + cOff + (row + 8) * CSTR + col * 2) = *(uint32_t*)&v1;
            }
        }
    }
}

// ---------------------------------------------------------------------------
__global__ __launch_bounds__(256, 2) void cnn_main_kernel(
    const float* __restrict__ w5g, const float* __restrict__ b5g,
    const int* __restrict__ uidxT, const int* __restrict__ iidxT,
    const int* __restrict__ uidxs, const int* __restrict__ iidxs,
    float* __restrict__ out)
{
    extern __shared__ char smb[];
    float* misc = (float*)(smb + OFF_MISC);
    int* nidx = (int*)(misc + MISC_NIDX);
    uint32_t sbase = (uint32_t)__cvta_generic_to_shared(smb);
    const int tid = threadIdx.x;
    const int b = blockIdx.x;

    // Phase 0: neighbor indices, w5/b5, zero B1 pad rows (k 100-103, 204-207)
    if (tid < 200) {
        nidx[tid] = (tid < 100) ? uidxT[(size_t)uidxs[b] * KN + tid]
                                : iidxT[(size_t)iidxs[b] * KN + (tid - 100)];
    } else if (tid < 232) {
        misc[MISC_W5 + tid - 200] = w5g[tid - 200];
    } else if (tid == 232) {
        misc[MISC_B5] = b5g[0];
    }
    if (tid < 72) {
        int rr = tid / 9, c = tid % 9;
        int row = (rr < 4) ? 100 + rr : 200 + rr;
        *(uint4*)(smb + OFF_B1 + row * 144 + c * 16) = make_uint4(0, 0, 0, 0);
    }
    __syncthreads();

    // Phase 1: gathers via cp.async (16B chunks)
    // A1 row r: u chunks 0-12 (cols 0-103), i chunks 13-25 (cols 104-207)
    for (int t = tid; t < 2600; t += 256) {
        int r = t / 26, c = t % 26;
        const char* src = (c < 13)
            ? (const char*)(g_uscr16 + (size_t)nidx[r] * 104) + c * 16
            : (const char*)(g_iscr16 + (size_t)nidx[100 + r] * 104) + (c - 13) * 16;
        CP_ASYNC16(sbase + OFF_A1 + (uint32_t)(r * 432 + c * 16), src);
    }
    // B1: k-major pe rows; j<100 -> rows 0-99 (user), j>=100 -> rows 104-203 (item)
    for (int t = tid; t < 1600; t += 256) {
        int j = t >> 3, c = t & 7;
        const char* src = (j < 100)
            ? (const char*)(g_pe_user + (size_t)nidx[j] * 64) + c * 16
            : (const char*)(g_pe_item + (size_t)nidx[j] * 64) + c * 16;
        int dr = (j < 100) ? j : j + 4;
        CP_ASYNC16(sbase + OFF_B1 + (uint32_t)(dr * 144 + c * 16), src);
    }
    for (int t = tid; t < 512; t += 256) {
        int o = t >> 3, c = t & 7;
        CP_ASYNC16(sbase + OFF_W2 + (uint32_t)(o * 144 + c * 16),
                   (const char*)(g_w2h + o * 64 + c * 8));
    }
    if (tid < 256) {
        int o = tid >> 3, c = tid & 7;
        CP_ASYNC16(sbase + OFF_W3 + (uint32_t)(o * 144 + c * 16),
                   (const char*)(g_w3h + o * 64 + c * 8));
    }
    if (tid < 128) {
        int o = tid >> 2, c = tid & 3;
        CP_ASYNC16(sbase + OFF_W4 + (uint32_t)(o * 80 + c * 16),
                   (const char*)(g_w4h + o * 32 + c * 8));
    }
    CP_COMMIT();
    CP_WAIT0();
    __syncthreads();

    const int lane = tid & 31, w = tid >> 5;
    const int mw = w >> 1, nw = w & 1;
    const int mtn = (mw == 3) ? 1 : 2;
    const int cc = (lane & 3) * 2;

    // GEMM1 (f16 acc): H1[112][64] = relu(A1[112][208] @ B1^T + b1), 13 k16 steps
    {
        __half2 bias2[4];
#pragma unroll
        for (int nt = 0; nt < 4; nt++)
            bias2[nt] = *(const __half2*)(g_b1h + nw * 32 + nt * 8 + cc);

        uint32_t aAddr[2];
#pragma unroll
        for (int mt = 0; mt < 2; mt++)
            aAddr[mt] = sbase + OFF_A1
                      + (uint32_t)(mw * 32 + mt * 16 + (lane & 15)) * 432u
                      + (uint32_t)((lane >> 4) << 4);
        uint32_t bAddr[4];
#pragma unroll
        for (int nt = 0; nt < 4; nt++)
            bAddr[nt] = sbase + OFF_B1 + (uint32_t)(lane & 15) * 144u
                      + (uint32_t)((nw * 4 + nt) << 4);

        uint32_t acc[2][4][2];
#pragma unroll
        for (int mt = 0; mt < 2; mt++)
#pragma unroll
            for (int nt = 0; nt < 4; nt++) { acc[mt][nt][0] = 0u; acc[mt][nt][1] = 0u; }

#pragma unroll
        for (int ks = 0; ks < 13; ks++) {
            uint32_t bq[4][2];
#pragma unroll
            for (int nt = 0; nt < 4; nt++) ldsm2t(bq[nt], bAddr[nt] + ks * 2304);
#pragma unroll
            for (int mt = 0; mt < 2; mt++) {
                if (mt < mtn) {
                    uint32_t a[4];
                    ldsm4(a, aAddr[mt] + ks * 32);
#pragma unroll
                    for (int nt = 0; nt < 4; nt++) mma_f16acc(acc[mt][nt], a, bq[nt]);
                }
            }
        }
        __syncthreads();   // all A1/B1 reads done before H1 overwrites A1 region

        const int r = lane >> 2;
        const __half2 z = __floats2half2_rn(0.f, 0.f);
#pragma unroll
        for (int mt = 0; mt < 2; mt++) {
            if (mt < mtn) {
                int row = mw * 32 + mt * 16 + r;
#pragma unroll
                for (int nt = 0; nt < 4; nt++) {
                    int col = nw * 32 + nt * 8 + cc;
                    __half2 v0 = __hmax2(__hadd2(*(__half2*)&acc[mt][nt][0], bias2[nt]), z);
                    __half2 v1 = __hmax2(__hadd2(*(__half2*)&acc[mt][nt][1], bias2[nt]), z);
                    *(uint32_t*)(smb + OFF_A1 + row * 144 + col * 2) = *(uint32_t*)&v0;
                    *(uint32_t*)(smb + OFF_A1 + (row + 8) * 144 + col * 2) = *(uint32_t*)&v1;
                }
            }
        }
    }
    __syncthreads();

    // Layers 2-4, f16 accumulation, activations ping-pong A1<->B1 regions
    layer_f16<4, 4, 144, 144, 144>(sbase, OFF_A1, OFF_W2, OFF_B1, g_b2h, smb);
    __syncthreads();
    layer_f16<4, 2, 144, 144, 80>(sbase, OFF_B1, OFF_W3, OFF_A1, g_b3h, smb);
    __syncthreads();
    layer_f16<2, 2, 80, 80, 80>(sbase, OFF_A1, OFF_W4, OFF_B1, g_b4h, smb);
    __syncthreads();

    // Layer 5 + sigmoid + mean over rows 0-99 (H4 @ OFF_B1, stride 80)
    if (tid < 100) {
        float s = misc[MISC_B5];
#pragma unroll
        for (int o2 = 0; o2 < 16; o2++) {
            __half2 h = *(__half2*)(smb + OFF_B1 + tid * 80 + o2 * 4);
            float2 f = __half22float2(h);
            s += f.x * misc[MISC_W5 + o2 * 2] + f.y * misc[MISC_W5 + o2 * 2 + 1];
        }
        misc[MISC_RED + tid] = 1.f / (1.f + __expf(-s));
    }
    __syncthreads();
    if (tid < 32) {
        float v = misc[MISC_RED + tid] + misc[MISC_RED + tid + 32] + misc[MISC_RED + tid + 64]
                + ((tid < 4) ? misc[MISC_RED + tid + 96] : 0.f);
#pragma unroll
        for (int off = 16; off; off >>= 1)
            v += __shfl_down_sync(0xffffffffu, v, off);
        if (tid == 0) out[b] = v * (1.f / 100.f);
    }
}

// ---------------------------------------------------------------------------
extern "C" void kernel_launch(void* const* d_in, const int* in_sizes, int n_in,
                              void* d_out, int out_size)
{
    const float* user_emb = (const float*)d_in[0];
    const float* item_emb = (const float*)d_in[1];
    const float* user_scr = (const float*)d_in[2];
    const float* item_scr = (const float*)d_in[3];
    const float* w1 = (const float*)d_in[4];
    const float* b1 = (const float*)d_in[5];
    const float* w2 = (const float*)d_in[6];
    const float* b2 = (const float*)d_in[7];
    const float* w3 = (const float*)d_in[8];
    const float* b3 = (const float*)d_in[9];
    const float* w4 = (const float*)d_in[10];
    const float* b4 = (const float*)d_in[11];
    const float* w5 = (const float*)d_in[12];
    const float* b5 = (const float*)d_in[13];
    const int* user_idx_tensor = (const int*)d_in[14];
    const int* item_idx_tensor = (const int*)d_in[15];
    const int* user_idxs = (const int*)d_in[16];
    const int* item_idxs = (const int*)d_in[17];
    float* out = (float*)d_out;

    pe_kernel<<<(NU + 255) / 256, 256>>>(user_emb, w1, 0, 0, NU);
    pe_kernel<<<(NI + 255) / 256, 256>>>(item_emb, w1, 64, 1, NI);
    scr_cvt_kernel<<<(NU * 13 + 255) / 256, 256>>>(user_scr, 0, NU);
    scr_cvt_kernel<<<(NI * 13 + 255) / 256, 256>>>(item_scr, 1, NI);
    wcvt_kernel<<<29, 256>>>(w2, w3, w4, b1, b2, b3, b4);

    cudaFuncSetAttribute(cnn_main_kernel,
                         cudaFuncAttributeMaxDynamicSharedMemorySize, SMEM_BYTES);
    cnn_main_kernel<<<BB, 256, SMEM_BYTES>>>(
        w5, b5,
        user_idx_tensor, item_idx_tensor, user_idxs, item_idxs,
        out);
}

// round 8
// speedup vs baseline: 1.3335x; 1.3335x over previous
#include <cuda_runtime.h>
#include <cuda_fp16.h>
#include <math.h>
#include <stdint.h>

#define NU 100000
#define NI 50000
#define KN 100
#define BB 8192

// Precomputed fp16 tables
__device__ __half g_pe_user[NU * 64];
__device__ __half g_pe_item[NI * 64];
__device__ __half g_uscr16[(size_t)NU * 112];   // scr rows padded to 112, cols 100-111 zero
__device__ __half g_iscr16[(size_t)NI * 112];
__device__ __half g_w2h[64 * 64];
__device__ __half g_w3h[32 * 64];
__device__ __half g_w4h[32 * 32];

// ---------------------------------------------------------------------------
// Main-kernel SMEM (byte offsets)  — identical to the 238us champion:
//   A1 [112 r][232 k-halves] stride 464B @ 0      (51968)
//   B1 [224 k][72 n] stride 144B         @ 51968  (32256)
//   W2 [64][72h]  stride 144             @ 84224  (9216)
//   W3 [32][72h]  stride 144             @ 93440  (4608)
//   W4 [32][40h]  stride 80              @ 98048  (2560)
//   MISC (floats)                        @ 100608 (1344)
// Total 101952 B -> 2 CTAs/SM
// ---------------------------------------------------------------------------
#define OFF_A1   0
#define OFF_B1   51968
#define OFF_W2   84224
#define OFF_W3   93440
#define OFF_W4   98048
#define OFF_MISC 100608
#define SMEM_BYTES 101952
// MISC float indices
#define MISC_W5   0
#define MISC_B5   32
#define MISC_RED  33
#define MISC_NIDX 136

#define CP_ASYNC16(dst, src) \
    asm volatile("cp.async.cg.shared.global [%0], [%1], 16;" :: "r"(dst), "l"(src))
#define CP_COMMIT() asm volatile("cp.async.commit_group;" ::: "memory")
#define CP_WAIT0()  asm volatile("cp.async.wait_group 0;" ::: "memory")

__device__ __forceinline__ void ldsm4(uint32_t (&r)[4], uint32_t a) {
    asm volatile("ldmatrix.sync.aligned.m8n8.x4.shared.b16 {%0,%1,%2,%3}, [%4];"
                 : "=r"(r[0]), "=r"(r[1]), "=r"(r[2]), "=r"(r[3]) : "r"(a));
}
__device__ __forceinline__ void ldsm2(uint32_t (&r)[2], uint32_t a) {
    asm volatile("ldmatrix.sync.aligned.m8n8.x2.shared.b16 {%0,%1}, [%2];"
                 : "=r"(r[0]), "=r"(r[1]) : "r"(a));
}
__device__ __forceinline__ void ldsm2t(uint32_t (&r)[2], uint32_t a) {
    asm volatile("ldmatrix.sync.aligned.m8n8.x2.trans.shared.b16 {%0,%1}, [%2];"
                 : "=r"(r[0]), "=r"(r[1]) : "r"(a));
}
__device__ __forceinline__ void mma_f32acc(float (&c)[4], const uint32_t (&a)[4],
                                           const uint32_t (&b)[2]) {
    asm volatile(
        "mma.sync.aligned.m16n8k16.row.col.f32.f16.f16.f32 "
        "{%0,%1,%2,%3}, {%4,%5,%6,%7}, {%8,%9}, {%0,%1,%2,%3};"
        : "+f"(c[0]), "+f"(c[1]), "+f"(c[2]), "+f"(c[3])
        : "r"(a[0]), "r"(a[1]), "r"(a[2]), "r"(a[3]), "r"(b[0]), "r"(b[1]));
}

__device__ __forceinline__ uint32_t h2_bits(float x, float y) {
    __half2 h = __floats2half2_rn(x, y);
    return *(uint32_t*)&h;
}
__device__ __forceinline__ void cvt_store4(char* dst, float4 v) {
    uint32_t lo = h2_bits(v.x, v.y), hi = h2_bits(v.z, v.w);
    uint2 u; u.x = lo; u.y = hi;
    *(uint2*)dst = u;
}

// ---------------------------------------------------------------------------
// pe_kernel (tensor core): 256 rows/block, each warp 2 m16 tiles;
// W1 smem load amortized 2x vs the 128-row version.
// ---------------------------------------------------------------------------
__global__ __launch_bounds__(256) void pe_kernel(
    const float* __restrict__ emb, const float* __restrict__ w1,
    int w1_off, int which, int nrows)
{
    __shared__ __half W1h[64 * 72];
    __shared__ __half E[256 * 72];
    __half* __restrict__ pe = which ? g_pe_item : g_pe_user;

    const int tid = threadIdx.x;
    const int rows0 = blockIdx.x * 256;

    for (int t = tid; t < 64 * 16; t += 256) {
        int o = t >> 4, k4 = t & 15;
        float4 v = *(const float4*)(w1 + o * 128 + w1_off + k4 * 4);
        cvt_store4((char*)(W1h + o * 72 + k4 * 4), v);
    }
    for (int t = tid; t < 256 * 16; t += 256) {
        int r = t >> 4, k4 = t & 15;
        int n = rows0 + r;
        float4 v = (n < nrows) ? *(const float4*)(emb + (size_t)n * 64 + k4 * 4)
                               : make_float4(0.f, 0.f, 0.f, 0.f);
        cvt_store4((char*)(E + r * 72 + k4 * 4), v);
    }
    __syncthreads();

    const int lane = tid & 31, w = tid >> 5;
    uint32_t sE = (uint32_t)__cvta_generic_to_shared(E);
    uint32_t sW = (uint32_t)__cvta_generic_to_shared(W1h);
    uint32_t aAddr[2];
#pragma unroll
    for (int mt = 0; mt < 2; mt++)
        aAddr[mt] = sE + (uint32_t)(w * 32 + mt * 16 + (lane & 15)) * 144u
                  + (uint32_t)((lane >> 4) << 4);
    uint32_t bAddr0 = sW + (uint32_t)(lane & 7) * 144u + (uint32_t)(((lane >> 3) & 1) << 4);

    float acc[2][8][4];
#pragma unroll
    for (int mt = 0; mt < 2; mt++)
#pragma unroll
        for (int nt = 0; nt < 8; nt++)
#pragma unroll
            for (int i = 0; i < 4; i++) acc[mt][nt][i] = 0.f;

#pragma unroll
    for (int ks = 0; ks < 4; ks++) {
        uint32_t a[2][4];
        ldsm4(a[0], aAddr[0] + ks * 32);
        ldsm4(a[1], aAddr[1] + ks * 32);
#pragma unroll
        for (int nt = 0; nt < 8; nt++) {
            uint32_t b[2];
            ldsm2(b, bAddr0 + (uint32_t)nt * 8u * 144u + ks * 32);
            mma_f32acc(acc[0][nt], a[0], b);
            mma_f32acc(acc[1][nt], a[1], b);
        }
    }

    int c0 = (lane & 3) * 2;
#pragma unroll
    for (int mt = 0; mt < 2; mt++) {
        int r0 = rows0 + w * 32 + mt * 16 + (lane >> 2);
#pragma unroll
        for (int nt = 0; nt < 8; nt++) {
            int col = nt * 8 + c0;
            if (r0 < nrows)
                *(__half2*)(pe + (size_t)r0 * 64 + col) =
                    __floats2half2_rn(acc[mt][nt][0], acc[mt][nt][1]);
            if (r0 + 8 < nrows)
                *(__half2*)(pe + (size_t)(r0 + 8) * 64 + col) =
                    __floats2half2_rn(acc[mt][nt][2], acc[mt][nt][3]);
        }
    }
}

// ---------------------------------------------------------------------------
// scr_cvt: fp32 scr [nrows][100] -> fp16 padded [nrows][112]
// ---------------------------------------------------------------------------
__global__ __launch_bounds__(256) void scr_cvt_kernel(
    const float* __restrict__ src, int which, int nrows)
{
    __half* __restrict__ dst = which ? g_iscr16 : g_uscr16;
    int total = nrows * 14;
    for (int t = blockIdx.x * 256 + threadIdx.x; t < total; t += gridDim.x * 256) {
        int n = t / 14, cb = t % 14;
        uint32_t o[4] = {0, 0, 0, 0};
        if (cb < 12) {
            float4 a = *(const float4*)(src + (size_t)n * 100 + cb * 8);
            float4 bq = *(const float4*)(src + (size_t)n * 100 + cb * 8 + 4);
            o[0] = h2_bits(a.x, a.y);  o[1] = h2_bits(a.z, a.w);
            o[2] = h2_bits(bq.x, bq.y); o[3] = h2_bits(bq.z, bq.w);
        } else if (cb == 12) {
            float4 a = *(const float4*)(src + (size_t)n * 100 + 96);
            o[0] = h2_bits(a.x, a.y);  o[1] = h2_bits(a.z, a.w);
        }
        uint4 v; v.x = o[0]; v.y = o[1]; v.z = o[2]; v.w = o[3];
        *(uint4*)(dst + (size_t)n * 112 + cb * 8) = v;
    }
}

__global__ __launch_bounds__(256) void wcvt_kernel(
    const float* __restrict__ w2, const float* __restrict__ w3,
    const float* __restrict__ w4)
{
    int t = blockIdx.x * 256 + threadIdx.x;
    if (t < 4096) g_w2h[t] = __float2half_rn(w2[t]);
    else if (t < 6144) g_w3h[t - 4096] = __float2half_rn(w3[t - 4096]);
    else if (t < 7168) g_w4h[t - 6144] = __float2half_rn(w4[t - 6144]);
}

// ---------------------------------------------------------------------------
// Block-cooperative MLP layer, fp32 accumulation (native HMMA path):
// A [112][K] row-major fp16, B weights [N][K] n-major fp16,
// C = relu(A@B^T + bias) stored fp16. Warp w: mw=w>>1 (2 m-tiles, mw==3 -> 1),
// nw=w&1 (NT n-tiles).
// ---------------------------------------------------------------------------
template <int KS, int NT, int ASTR, int BSTR, int CSTR>
__device__ __forceinline__ void layer_f32(
    uint32_t sbase, int aOff, int bOff, int cOff,
    const float* __restrict__ bias, char* __restrict__ smb)
{
    const int lane = threadIdx.x & 31;
    const int w = threadIdx.x >> 5;
    const int mw = w >> 1, nw = w & 1;
    const int mtn = (mw == 3) ? 1 : 2;
    const int cc = (lane & 3) * 2;

    float2 bias2[NT];
#pragma unroll
    for (int nt = 0; nt < NT; nt++)
        bias2[nt] = *(const float2*)(bias + nw * NT * 8 + nt * 8 + cc);

    uint32_t aAddr[2];
#pragma unroll
    for (int mt = 0; mt < 2; mt++)
        aAddr[mt] = sbase + (uint32_t)aOff
                  + (uint32_t)(mw * 32 + mt * 16 + (lane & 15)) * ASTR
                  + (uint32_t)((lane >> 4) << 4);
    uint32_t bAddr[NT];
#pragma unroll
    for (int nt = 0; nt < NT; nt++)
        bAddr[nt] = sbase + (uint32_t)bOff
                  + (uint32_t)(nw * NT * 8 + nt * 8 + (lane & 7)) * BSTR
                  + (uint32_t)(((lane >> 3) & 1) << 4);

    float acc[2][NT][4];
#pragma unroll
    for (int mt = 0; mt < 2; mt++)
#pragma unroll
        for (int nt = 0; nt < NT; nt++)
#pragma unroll
            for (int i = 0; i < 4; i++) acc[mt][nt][i] = 0.f;

#pragma unroll
    for (int ks = 0; ks < KS; ks++) {
        uint32_t b[NT][2];
#pragma unroll
        for (int nt = 0; nt < NT; nt++) ldsm2(b[nt], bAddr[nt] + ks * 32);
#pragma unroll
        for (int mt = 0; mt < 2; mt++) {
            if (mt < mtn) {
                uint32_t a[4];
                ldsm4(a, aAddr[mt] + ks * 32);
#pragma unroll
                for (int nt = 0; nt < NT; nt++) mma_f32acc(acc[mt][nt], a, b[nt]);
            }
        }
    }

    const int r = lane >> 2;
#pragma unroll
    for (int mt = 0; mt < 2; mt++) {
        if (mt < mtn) {
            int row = mw * 32 + mt * 16 + r;
#pragma unroll
            for (int nt = 0; nt < NT; nt++) {
                int col = nw * NT * 8 + nt * 8 + cc;
                *(uint32_t*)(smb + cOff + row * CSTR + col * 2) =
                    h2_bits(fmaxf(acc[mt][nt][0] + bias2[nt].x, 0.f),
                            fmaxf(acc[mt][nt][1] + bias2[nt].y, 0.f));
                *(uint32_t*)(smb + cOff + (row + 8) * CSTR + col * 2) =
                    h2_bits(fmaxf(acc[mt][nt][2] + bias2[nt].x, 0.f),
                            fmaxf(acc[mt][nt][3] + bias2[nt].y, 0.f));
            }
        }
    }
}

// ---------------------------------------------------------------------------
__global__ __launch_bounds__(256, 2) void cnn_main_kernel(
    const float* __restrict__ b1g, const float* __restrict__ b2g,
    const float* __restrict__ b3g, const float* __restrict__ b4g,
    const float* __restrict__ w5g, const float* __restrict__ b5g,
    const int* __restrict__ uidxT, const int* __restrict__ iidxT,
    const int* __restrict__ uidxs, const int* __restrict__ iidxs,
    float* __restrict__ out)
{
    extern __shared__ char smb[];
    float* misc = (float*)(smb + OFF_MISC);
    int* nidx = (int*)(misc + MISC_NIDX);
    uint32_t sbase = (uint32_t)__cvta_generic_to_shared(smb);
    const int tid = threadIdx.x;
    const int b = blockIdx.x;

    // Phase 0: neighbor indices, w5/b5, zero B1 pad rows (k 100-111, 212-223)
    if (tid < 200) {
        nidx[tid] = (tid < 100) ? uidxT[(size_t)uidxs[b] * KN + tid]
                                : iidxT[(size_t)iidxs[b] * KN + (tid - 100)];
    } else if (tid < 232) {
        misc[MISC_W5 + tid - 200] = w5g[tid - 200];
    } else if (tid == 232) {
        misc[MISC_B5] = b5g[0];
    }
    if (tid < 192) {
        int rr = tid >> 3;
        int row = (rr < 12) ? 100 + rr : 200 + rr;
        *(uint4*)(smb + OFF_B1 + row * 144 + (tid & 7) * 16) = make_uint4(0, 0, 0, 0);
    }
    __syncthreads();

    // Phase 1: all gathers via cp.async (16B chunks)
    for (int t = tid; t < 2800; t += 256) {
        int r = t / 28, c = t % 28;
        const char* src = (c < 14)
            ? (const char*)(g_uscr16 + (size_t)nidx[r] * 112) + c * 16
            : (const char*)(g_iscr16 + (size_t)nidx[100 + r] * 112) + (c - 14) * 16;
        CP_ASYNC16(sbase + OFF_A1 + (uint32_t)(r * 464 + c * 16), src);
    }
    for (int t = tid; t < 1600; t += 256) {
        int j = t >> 3, c = t & 7;
        const char* src = (j < 100)
            ? (const char*)(g_pe_user + (size_t)nidx[j] * 64) + c * 16
            : (const char*)(g_pe_item + (size_t)nidx[j] * 64) + c * 16;
        int dr = (j < 100) ? j : j + 12;
        CP_ASYNC16(sbase + OFF_B1 + (uint32_t)(dr * 144 + c * 16), src);
    }
    for (int t = tid; t < 512; t += 256) {
        int o = t >> 3, c = t & 7;
        CP_ASYNC16(sbase + OFF_W2 + (uint32_t)(o * 144 + c * 16),
                   (const char*)(g_w2h + o * 64 + c * 8));
    }
    if (tid < 256) {
        int o = tid >> 3, c = tid & 7;
        CP_ASYNC16(sbase + OFF_W3 + (uint32_t)(o * 144 + c * 16),
                   (const char*)(g_w3h + o * 64 + c * 8));
    }
    if (tid < 128) {
        int o = tid >> 2, c = tid & 3;
        CP_ASYNC16(sbase + OFF_W4 + (uint32_t)(o * 80 + c * 16),
                   (const char*)(g_w4h + o * 32 + c * 8));
    }
    CP_COMMIT();
    CP_WAIT0();
    __syncthreads();

    const int lane = tid & 31, w = tid >> 5;
    const int mw = w >> 1, nw = w & 1;
    const int mtn = (mw == 3) ? 1 : 2;
    const int cc = (lane & 3) * 2;

    // GEMM1 (fp32 acc): H1[112][64] = relu(A1[112][224] @ B1^T + b1), 14 k16 steps
    {
        float2 bfrag[4];
#pragma unroll
        for (int nt = 0; nt < 4; nt++)
            bfrag[nt] = *(const float2*)(b1g + nw * 32 + nt * 8 + cc);

        uint32_t aAddr[2];
#pragma unroll
        for (int mt = 0; mt < 2; mt++)
            aAddr[mt] = sbase + OFF_A1
                      + (uint32_t)(mw * 32 + mt * 16 + (lane & 15)) * 464u
                      + (uint32_t)((lane >> 4) << 4);
        uint32_t bAddr[4];
#pragma unroll
        for (int nt = 0; nt < 4; nt++)
            bAddr[nt] = sbase + OFF_B1 + (uint32_t)(lane & 15) * 144u
                      + (uint32_t)((nw * 4 + nt) << 4);

        float acc[2][4][4];
#pragma unroll
        for (int mt = 0; mt < 2; mt++)
#pragma unroll
            for (int nt = 0; nt < 4; nt++)
#pragma unroll
                for (int i = 0; i < 4; i++) acc[mt][nt][i] = 0.f;

#pragma unroll
        for (int ks = 0; ks < 14; ks++) {
            uint32_t bq[4][2];
#pragma unroll
            for (int nt = 0; nt < 4; nt++) ldsm2t(bq[nt], bAddr[nt] + ks * 2304);
#pragma unroll
            for (int mt = 0; mt < 2; mt++) {
                if (mt < mtn) {
                    uint32_t a[4];
                    ldsm4(a, aAddr[mt] + ks * 32);
#pragma unroll
                    for (int nt = 0; nt < 4; nt++) mma_f32acc(acc[mt][nt], a, bq[nt]);
                }
            }
        }
        __syncthreads();   // all A1/B1 reads done before H1 overwrites A1 region

        const int r = lane >> 2;
#pragma unroll
        for (int mt = 0; mt < 2; mt++) {
            if (mt < mtn) {
                int row = mw * 32 + mt * 16 + r;
#pragma unroll
                for (int nt = 0; nt < 4; nt++) {
                    int col = nw * 32 + nt * 8 + cc;
                    *(uint32_t*)(smb + OFF_A1 + row * 144 + col * 2) =
                        h2_bits(fmaxf(acc[mt][nt][0] + bfrag[nt].x, 0.f),
                                fmaxf(acc[mt][nt][1] + bfrag[nt].y, 0.f));
                    *(uint32_t*)(smb + OFF_A1 + (row + 8) * 144 + col * 2) =
                        h2_bits(fmaxf(acc[mt][nt][2] + bfrag[nt].x, 0.f),
                                fmaxf(acc[mt][nt][3] + bfrag[nt].y, 0.f));
                }
            }
        }
    }
    __syncthreads();

    // Layers 2-4, fp32 accumulation, activations ping-pong A1<->B1 regions
    layer_f32<4, 4, 144, 144, 144>(sbase, OFF_A1, OFF_W2, OFF_B1, b2g, smb);
    __syncthreads();
    layer_f32<4, 2, 144, 144, 80>(sbase, OFF_B1, OFF_W3, OFF_A1, b3g, smb);
    __syncthreads();
    layer_f32<2, 2, 80, 80, 80>(sbase, OFF_A1, OFF_W4, OFF_B1, b4g, smb);
    __syncthreads();

    // Layer 5 + sigmoid + mean over rows 0-99 (H4 @ OFF_B1, stride 80)
    if (tid < 100) {
        float s = misc[MISC_B5];
#pragma unroll
        for (int o2 = 0; o2 < 16; o2++) {
            __half2 h = *(__half2*)(smb + OFF_B1 + tid * 80 + o2 * 4);
            float2 f = __half22float2(h);
            s += f.x * misc[MISC_W5 + o2 * 2] + f.y * misc[MISC_W5 + o2 * 2 + 1];
        }
        misc[MISC_RED + tid] = 1.f / (1.f + __expf(-s));
    }
    __syncthreads();
    if (tid < 32) {
        float v = misc[MISC_RED + tid] + misc[MISC_RED + tid + 32] + misc[MISC_RED + tid + 64]
                + ((tid < 4) ? misc[MISC_RED + tid + 96] : 0.f);
#pragma unroll
        for (int off = 16; off; off >>= 1)
            v += __shfl_down_sync(0xffffffffu, v, off);
        if (tid == 0) out[b] = v * (1.f / 100.f);
    }
}

// ---------------------------------------------------------------------------
extern "C" void kernel_launch(void* const* d_in, const int* in_sizes, int n_in,
                              void* d_out, int out_size)
{
    const float* user_emb = (const float*)d_in[0];
    const float* item_emb = (const float*)d_in[1];
    const float* user_scr = (const float*)d_in[2];
    const float* item_scr = (const float*)d_in[3];
    const float* w1 = (const float*)d_in[4];
    const float* b1 = (const float*)d_in[5];
    const float* w2 = (const float*)d_in[6];
    const float* b2 = (const float*)d_in[7];
    const float* w3 = (const float*)d_in[8];
    const float* b3 = (const float*)d_in[9];
    const float* w4 = (const float*)d_in[10];
    const float* b4 = (const float*)d_in[11];
    const float* w5 = (const float*)d_in[12];
    const float* b5 = (const float*)d_in[13];
    const int* user_idx_tensor = (const int*)d_in[14];
    const int* item_idx_tensor = (const int*)d_in[15];
    const int* user_idxs = (const int*)d_in[16];
    const int* item_idxs = (const int*)d_in[17];
    float* out = (float*)d_out;

    pe_kernel<<<(NU + 255) / 256, 256>>>(user_emb, w1, 0, 0, NU);
    pe_kernel<<<(NI + 255) / 256, 256>>>(item_emb, w1, 64, 1, NI);
    scr_cvt_kernel<<<(NU * 14 + 255) / 256, 256>>>(user_scr, 0, NU);
    scr_cvt_kernel<<<(NI * 14 + 255) / 256, 256>>>(item_scr, 1, NI);
    wcvt_kernel<<<28, 256>>>(w2, w3, w4);

    cudaFuncSetAttribute(cnn_main_kernel,
                         cudaFuncAttributeMaxDynamicSharedMemorySize, SMEM_BYTES);
    cnn_main_kernel<<<BB, 256, SMEM_BYTES>>>(
        b1, b2, b3, b4, w5, b5,
        user_idx_tensor, item_idx_tensor, user_idxs, item_idxs,
        out);
}

// round 9
// speedup vs baseline: 1.3600x; 1.0198x over previous
#include <cuda_runtime.h>
#include <cuda_fp16.h>
#include <math.h>
#include <stdint.h>

#define NU 100000
#define NI 50000
#define KN 100
#define BB 8192

// Precomputed fp16 tables
__device__ __half g_pe_user[NU * 64];
__device__ __half g_pe_item[NI * 64];
__device__ __half g_uscr16[(size_t)NU * 112];   // scr rows padded to 112, cols 100-111 zero
__device__ __half g_iscr16[(size_t)NI * 112];
__device__ __half g_w2h[64 * 64];
__device__ __half g_w3h[32 * 64];
__device__ __half g_w4h[32 * 32];
__device__ __half g_b2h[64];
__device__ __half g_b3h[32];
__device__ __half g_b4h[32];

// ---------------------------------------------------------------------------
// Main-kernel SMEM (byte offsets) — identical to the 238us champion:
//   A1 [112 r][232 k-halves] stride 464B @ 0      (51968)
//   B1 [224 k][72 n] stride 144B         @ 51968  (32256)
//   W2 [64][72h]  stride 144             @ 84224  (9216)
//   W3 [32][72h]  stride 144             @ 93440  (4608)
//   W4 [32][40h]  stride 80              @ 98048  (2560)
//   MISC (floats)                        @ 100608 (1344)
// Total 101952 B -> 2 CTAs/SM
// ---------------------------------------------------------------------------
#define OFF_A1   0
#define OFF_B1   51968
#define OFF_W2   84224
#define OFF_W3   93440
#define OFF_W4   98048
#define OFF_MISC 100608
#define SMEM_BYTES 101952
// MISC float indices
#define MISC_W5   0
#define MISC_B5   32
#define MISC_RED  33
#define MISC_NIDX 136

#define CP_ASYNC16(dst, src) \
    asm volatile("cp.async.cg.shared.global [%0], [%1], 16;" :: "r"(dst), "l"(src))
#define CP_COMMIT() asm volatile("cp.async.commit_group;" ::: "memory")
#define CP_WAIT0()  asm volatile("cp.async.wait_group 0;" ::: "memory")

__device__ __forceinline__ void ldsm4(uint32_t (&r)[4], uint32_t a) {
    asm volatile("ldmatrix.sync.aligned.m8n8.x4.shared.b16 {%0,%1,%2,%3}, [%4];"
                 : "=r"(r[0]), "=r"(r[1]), "=r"(r[2]), "=r"(r[3]) : "r"(a));
}
__device__ __forceinline__ void ldsm2(uint32_t (&r)[2], uint32_t a) {
    asm volatile("ldmatrix.sync.aligned.m8n8.x2.shared.b16 {%0,%1}, [%2];"
                 : "=r"(r[0]), "=r"(r[1]) : "r"(a));
}
__device__ __forceinline__ void ldsm4t(uint32_t (&r)[4], uint32_t a) {
    asm volatile("ldmatrix.sync.aligned.m8n8.x4.trans.shared.b16 {%0,%1,%2,%3}, [%4];"
                 : "=r"(r[0]), "=r"(r[1]), "=r"(r[2]), "=r"(r[3]) : "r"(a));
}
__device__ __forceinline__ void mma_f32acc(float (&c)[4], const uint32_t (&a)[4],
                                           const uint32_t* b) {
    asm volatile(
        "mma.sync.aligned.m16n8k16.row.col.f32.f16.f16.f32 "
        "{%0,%1,%2,%3}, {%4,%5,%6,%7}, {%8,%9}, {%0,%1,%2,%3};"
        : "+f"(c[0]), "+f"(c[1]), "+f"(c[2]), "+f"(c[3])
        : "r"(a[0]), "r"(a[1]), "r"(a[2]), "r"(a[3]), "r"(b[0]), "r"(b[1]));
}
__device__ __forceinline__ void mma_f16acc(uint32_t (&c)[2], const uint32_t (&a)[4],
                                           const uint32_t* b) {
    asm volatile(
        "mma.sync.aligned.m16n8k16.row.col.f16.f16.f16.f16 "
        "{%0,%1}, {%2,%3,%4,%5}, {%6,%7}, {%0,%1};"
        : "+r"(c[0]), "+r"(c[1])
        : "r"(a[0]), "r"(a[1]), "r"(a[2]), "r"(a[3]), "r"(b[0]), "r"(b[1]));
}

__device__ __forceinline__ uint32_t h2_bits(float x, float y) {
    __half2 h = __floats2half2_rn(x, y);
    return *(uint32_t*)&h;
}
__device__ __forceinline__ void cvt_store4(char* dst, float4 v) {
    uint32_t lo = h2_bits(v.x, v.y), hi = h2_bits(v.z, v.w);
    uint2 u; u.x = lo; u.y = hi;
    *(uint2*)dst = u;
}

// ---------------------------------------------------------------------------
// pe_kernel (tensor core): 256 rows/block, each warp 2 m16 tiles.
// ---------------------------------------------------------------------------
__global__ __launch_bounds__(256) void pe_kernel(
    const float* __restrict__ emb, const float* __restrict__ w1,
    int w1_off, int which, int nrows)
{
    __shared__ __half W1h[64 * 72];
    __shared__ __half E[256 * 72];
    __half* __restrict__ pe = which ? g_pe_item : g_pe_user;

    const int tid = threadIdx.x;
    const int rows0 = blockIdx.x * 256;

    for (int t = tid; t < 64 * 16; t += 256) {
        int o = t >> 4, k4 = t & 15;
        float4 v = *(const float4*)(w1 + o * 128 + w1_off + k4 * 4);
        cvt_store4((char*)(W1h + o * 72 + k4 * 4), v);
    }
    for (int t = tid; t < 256 * 16; t += 256) {
        int r = t >> 4, k4 = t & 15;
        int n = rows0 + r;
        float4 v = (n < nrows) ? *(const float4*)(emb + (size_t)n * 64 + k4 * 4)
                               : make_float4(0.f, 0.f, 0.f, 0.f);
        cvt_store4((char*)(E + r * 72 + k4 * 4), v);
    }
    __syncthreads();

    const int lane = tid & 31, w = tid >> 5;
    uint32_t sE = (uint32_t)__cvta_generic_to_shared(E);
    uint32_t sW = (uint32_t)__cvta_generic_to_shared(W1h);
    uint32_t aAddr[2];
#pragma unroll
    for (int mt = 0; mt < 2; mt++)
        aAddr[mt] = sE + (uint32_t)(w * 32 + mt * 16 + (lane & 15)) * 144u
                  + (uint32_t)((lane >> 4) << 4);
    uint32_t bAddr0 = sW + (uint32_t)(lane & 7) * 144u + (uint32_t)(((lane >> 3) & 1) << 4);

    float acc[2][8][4];
#pragma unroll
    for (int mt = 0; mt < 2; mt++)
#pragma unroll
        for (int nt = 0; nt < 8; nt++)
#pragma unroll
            for (int i = 0; i < 4; i++) acc[mt][nt][i] = 0.f;

#pragma unroll
    for (int ks = 0; ks < 4; ks++) {
        uint32_t a[2][4];
        ldsm4(a[0], aAddr[0] + ks * 32);
        ldsm4(a[1], aAddr[1] + ks * 32);
#pragma unroll
        for (int nt = 0; nt < 8; nt++) {
            uint32_t b[2];
            ldsm2(b, bAddr0 + (uint32_t)nt * 8u * 144u + ks * 32);
            mma_f32acc(acc[0][nt], a[0], b);
            mma_f32acc(acc[1][nt], a[1], b);
        }
    }

    int c0 = (lane & 3) * 2;
#pragma unroll
    for (int mt = 0; mt < 2; mt++) {
        int r0 = rows0 + w * 32 + mt * 16 + (lane >> 2);
#pragma unroll
        for (int nt = 0; nt < 8; nt++) {
            int col = nt * 8 + c0;
            if (r0 < nrows)
                *(__half2*)(pe + (size_t)r0 * 64 + col) =
                    __floats2half2_rn(acc[mt][nt][0], acc[mt][nt][1]);
            if (r0 + 8 < nrows)
                *(__half2*)(pe + (size_t)(r0 + 8) * 64 + col) =
                    __floats2half2_rn(acc[mt][nt][2], acc[mt][nt][3]);
        }
    }
}

// ---------------------------------------------------------------------------
// scr_cvt: fp32 scr [nrows][100] -> fp16 padded [nrows][112]
// ---------------------------------------------------------------------------
__global__ __launch_bounds__(256) void scr_cvt_kernel(
    const float* __restrict__ src, int which, int nrows)
{
    __half* __restrict__ dst = which ? g_iscr16 : g_uscr16;
    int total = nrows * 14;
    for (int t = blockIdx.x * 256 + threadIdx.x; t < total; t += gridDim.x * 256) {
        int n = t / 14, cb = t % 14;
        uint32_t o[4] = {0, 0, 0, 0};
        if (cb < 12) {
            float4 a = *(const float4*)(src + (size_t)n * 100 + cb * 8);
            float4 bq = *(const float4*)(src + (size_t)n * 100 + cb * 8 + 4);
            o[0] = h2_bits(a.x, a.y);  o[1] = h2_bits(a.z, a.w);
            o[2] = h2_bits(bq.x, bq.y); o[3] = h2_bits(bq.z, bq.w);
        } else if (cb == 12) {
            float4 a = *(const float4*)(src + (size_t)n * 100 + 96);
            o[0] = h2_bits(a.x, a.y);  o[1] = h2_bits(a.z, a.w);
        }
        uint4 v; v.x = o[0]; v.y = o[1]; v.z = o[2]; v.w = o[3];
        *(uint4*)(dst + (size_t)n * 112 + cb * 8) = v;
    }
}

__global__ __launch_bounds__(256) void wcvt_kernel(
    const float* __restrict__ w2, const float* __restrict__ w3,
    const float* __restrict__ w4, const float* __restrict__ b2,
    const float* __restrict__ b3, const float* __restrict__ b4)
{
    int t = blockIdx.x * 256 + threadIdx.x;
    if (t < 4096) g_w2h[t] = __float2half_rn(w2[t]);
    else if (t < 6144) g_w3h[t - 4096] = __float2half_rn(w3[t - 4096]);
    else if (t < 7168) g_w4h[t - 6144] = __float2half_rn(w4[t - 6144]);
    else if (t < 7232) g_b2h[t - 7168] = __float2half_rn(b2[t - 7168]);
    else if (t < 7264) g_b3h[t - 7232] = __float2half_rn(b3[t - 7232]);
    else if (t < 7296) g_b4h[t - 7264] = __float2half_rn(b4[t - 7264]);
}

// ---------------------------------------------------------------------------
// Block-cooperative f16-acc MLP layer (R5 structure), x4 B-frag loads:
// A [112][K] row-major, B weights [N][K] n-major, C = relu(A@B^T + bias) fp16.
// Warp w: mw=w>>1 (2 m-tiles, mw==3 -> 1), nw=w&1 (NT n-tiles, NT even).
// ---------------------------------------------------------------------------
template <int KS, int NT, int ASTR, int BSTR, int CSTR>
__device__ __forceinline__ void layer_f16(
    uint32_t sbase, int aOff, int bOff, int cOff,
    const __half* __restrict__ bias, char* __restrict__ smb)
{
    const int lane = threadIdx.x & 31;
    const int w = threadIdx.x >> 5;
    const int mw = w >> 1, nw = w & 1;
    const int mtn = (mw == 3) ? 1 : 2;
    const int cc = (lane & 3) * 2;
    constexpr int NP = NT / 2;

    __half2 bias2[NT];
#pragma unroll
    for (int nt = 0; nt < NT; nt++)
        bias2[nt] = *(const __half2*)(bias + nw * NT * 8 + nt * 8 + cc);

    uint32_t aAddr[2];
#pragma unroll
    for (int mt = 0; mt < 2; mt++)
        aAddr[mt] = sbase + (uint32_t)aOff
                  + (uint32_t)(mw * 32 + mt * 16 + (lane & 15)) * ASTR
                  + (uint32_t)((lane >> 4) << 4);
    // x4 B loads: lane groups 0-15 -> n-tile 2j, 16-31 -> n-tile 2j+1
    uint32_t bAddr[NP];
#pragma unroll
    for (int j = 0; j < NP; j++) {
        int nrow = nw * NT * 8 + (j * 2 + (lane >> 4)) * 8 + (lane & 7);
        bAddr[j] = sbase + (uint32_t)bOff + (uint32_t)nrow * BSTR
                 + (uint32_t)(((lane >> 3) & 1) << 4);
    }

    uint32_t acc[2][NT][2];
#pragma unroll
    for (int mt = 0; mt < 2; mt++)
#pragma unroll
        for (int nt = 0; nt < NT; nt++) { acc[mt][nt][0] = 0u; acc[mt][nt][1] = 0u; }

#pragma unroll
    for (int ks = 0; ks < KS; ks++) {
        uint32_t b[NP][4];
#pragma unroll
        for (int j = 0; j < NP; j++) ldsm4(b[j], bAddr[j] + ks * 32);
#pragma unroll
        for (int mt = 0; mt < 2; mt++) {
            if (mt < mtn) {
                uint32_t a[4];
                ldsm4(a, aAddr[mt] + ks * 32);
#pragma unroll
                for (int j = 0; j < NP; j++) {
                    mma_f16acc(acc[mt][j * 2 + 0], a, &b[j][0]);
                    mma_f16acc(acc[mt][j * 2 + 1], a, &b[j][2]);
                }
            }
        }
    }

    const int r = lane >> 2;
    const __half2 z = __floats2half2_rn(0.f, 0.f);
#pragma unroll
    for (int mt = 0; mt < 2; mt++) {
        if (mt < mtn) {
            int row = mw * 32 + mt * 16 + r;
#pragma unroll
            for (int nt = 0; nt < NT; nt++) {
                int col = nw * NT * 8 + nt * 8 + cc;
                __half2 v0 = __hmax2(__hadd2(*(__half2*)&acc[mt][nt][0], bias2[nt]), z);
                __half2 v1 = __hmax2(__hadd2(*(__half2*)&acc[mt][nt][1], bias2[nt]), z);
                *(uint32_t*)(smb + cOff + row * CSTR + col * 2) = *(uint32_t*)&v0;
                *(uint32_t*)(smb + cOff + (row + 8) * CSTR + col * 2) = *(uint32_t*)&v1;
            }
        }
    }
}

// ---------------------------------------------------------------------------
__global__ __launch_bounds__(256, 2) void cnn_main_kernel(
    const float* __restrict__ b1g,
    const float* __restrict__ w5g, const float* __restrict__ b5g,
    const int* __restrict__ uidxT, const int* __restrict__ iidxT,
    const int* __restrict__ uidxs, const int* __restrict__ iidxs,
    float* __restrict__ out)
{
    extern __shared__ char smb[];
    float* misc = (float*)(smb + OFF_MISC);
    int* nidx = (int*)(misc + MISC_NIDX);
    uint32_t sbase = (uint32_t)__cvta_generic_to_shared(smb);
    const int tid = threadIdx.x;
    const int b = blockIdx.x;

    // Phase 0: neighbor indices, w5/b5, zero B1 pad rows (k 100-111, 212-223)
    if (tid < 200) {
        nidx[tid] = (tid < 100) ? uidxT[(size_t)uidxs[b] * KN + tid]
                                : iidxT[(size_t)iidxs[b] * KN + (tid - 100)];
    } else if (tid < 232) {
        misc[MISC_W5 + tid - 200] = w5g[tid - 200];
    } else if (tid == 232) {
        misc[MISC_B5] = b5g[0];
    }
    if (tid < 192) {
        int rr = tid >> 3;
        int row = (rr < 12) ? 100 + rr : 200 + rr;
        *(uint4*)(smb + OFF_B1 + row * 144 + (tid & 7) * 16) = make_uint4(0, 0, 0, 0);
    }
    __syncthreads();

    // Phase 1: all gathers via cp.async (16B chunks)
    for (int t = tid; t < 2800; t += 256) {
        int r = t / 28, c = t % 28;
        const char* src = (c < 14)
            ? (const char*)(g_uscr16 + (size_t)nidx[r] * 112) + c * 16
            : (const char*)(g_iscr16 + (size_t)nidx[100 + r] * 112) + (c - 14) * 16;
        CP_ASYNC16(sbase + OFF_A1 + (uint32_t)(r * 464 + c * 16), src);
    }
    for (int t = tid; t < 1600; t += 256) {
        int j = t >> 3, c = t & 7;
        const char* src = (j < 100)
            ? (const char*)(g_pe_user + (size_t)nidx[j] * 64) + c * 16
            : (const char*)(g_pe_item + (size_t)nidx[j] * 64) + c * 16;
        int dr = (j < 100) ? j : j + 12;
        CP_ASYNC16(sbase + OFF_B1 + (uint32_t)(dr * 144 + c * 16), src);
    }
    for (int t = tid; t < 512; t += 256) {
        int o = t >> 3, c = t & 7;
        CP_ASYNC16(sbase + OFF_W2 + (uint32_t)(o * 144 + c * 16),
                   (const char*)(g_w2h + o * 64 + c * 8));
    }
    if (tid < 256) {
        int o = tid >> 3, c = tid & 7;
        CP_ASYNC16(sbase + OFF_W3 + (uint32_t)(o * 144 + c * 16),
                   (const char*)(g_w3h + o * 64 + c * 8));
    }
    if (tid < 128) {
        int o = tid >> 2, c = tid & 3;
        CP_ASYNC16(sbase + OFF_W4 + (uint32_t)(o * 80 + c * 16),
                   (const char*)(g_w4h + o * 32 + c * 8));
    }
    CP_COMMIT();
    CP_WAIT0();
    __syncthreads();

    const int lane = tid & 31, w = tid >> 5;
    const int mw = w >> 1, nw = w & 1;
    const int mtn = (mw == 3) ? 1 : 2;
    const int cc = (lane & 3) * 2;

    // GEMM1 (fp32 acc): H1[112][64] = relu(A1[112][224] @ B1^T + b1), 14 k16 steps
    // B1 k-major -> x4 trans ldmatrix, lane groups 16-31 take the next n-tile.
    {
        float2 bfrag[4];
#pragma unroll
        for (int nt = 0; nt < 4; nt++)
            bfrag[nt] = *(const float2*)(b1g + nw * 32 + nt * 8 + cc);

        uint32_t aAddr[2];
#pragma unroll
        for (int mt = 0; mt < 2; mt++)
            aAddr[mt] = sbase + OFF_A1
                      + (uint32_t)(mw * 32 + mt * 16 + (lane & 15)) * 464u
                      + (uint32_t)((lane >> 4) << 4);
        uint32_t bAddr[2];
#pragma unroll
        for (int j = 0; j < 2; j++)
            bAddr[j] = sbase + OFF_B1 + (uint32_t)(lane & 15) * 144u
                     + (uint32_t)((nw * 4 + j * 2 + (lane >> 4)) << 4);

        float acc[2][4][4];
#pragma unroll
        for (int mt = 0; mt < 2; mt++)
#pragma unroll
            for (int nt = 0; nt < 4; nt++)
#pragma unroll
                for (int i = 0; i < 4; i++) acc[mt][nt][i] = 0.f;

#pragma unroll
        for (int ks = 0; ks < 14; ks++) {
            uint32_t bq[2][4];
            ldsm4t(bq[0], bAddr[0] + ks * 2304);
            ldsm4t(bq[1], bAddr[1] + ks * 2304);
#pragma unroll
            for (int mt = 0; mt < 2; mt++) {
                if (mt < mtn) {
                    uint32_t a[4];
                    ldsm4(a, aAddr[mt] + ks * 32);
                    mma_f32acc(acc[mt][0], a, &bq[0][0]);
                    mma_f32acc(acc[mt][1], a, &bq[0][2]);
                    mma_f32acc(acc[mt][2], a, &bq[1][0]);
                    mma_f32acc(acc[mt][3], a, &bq[1][2]);
                }
            }
        }
        __syncthreads();   // all A1/B1 reads done before H1 overwrites A1 region

        const int r = lane >> 2;
#pragma unroll
        for (int mt = 0; mt < 2; mt++) {
            if (mt < mtn) {
                int row = mw * 32 + mt * 16 + r;
#pragma unroll
                for (int nt = 0; nt < 4; nt++) {
                    int col = nw * 32 + nt * 8 + cc;
                    *(uint32_t*)(smb + OFF_A1 + row * 144 + col * 2) =
                        h2_bits(fmaxf(acc[mt][nt][0] + bfrag[nt].x, 0.f),
                                fmaxf(acc[mt][nt][1] + bfrag[nt].y, 0.f));
                    *(uint32_t*)(smb + OFF_A1 + (row + 8) * 144 + col * 2) =
                        h2_bits(fmaxf(acc[mt][nt][2] + bfrag[nt].x, 0.f),
                                fmaxf(acc[mt][nt][3] + bfrag[nt].y, 0.f));
                }
            }
        }
    }
    __syncthreads();

    // Layers 2-4, f16 accumulation (R5 champion mix), ping-pong A1<->B1
    layer_f16<4, 4, 144, 144, 144>(sbase, OFF_A1, OFF_W2, OFF_B1, g_b2h, smb);
    __syncthreads();
    layer_f16<4, 2, 144, 144, 80>(sbase, OFF_B1, OFF_W3, OFF_A1, g_b3h, smb);
    __syncthreads();
    layer_f16<2, 2, 80, 80, 80>(sbase, OFF_A1, OFF_W4, OFF_B1, g_b4h, smb);
    __syncthreads();

    // Layer 5 + sigmoid + mean over rows 0-99 (H4 @ OFF_B1, stride 80)
    if (tid < 100) {
        float s = misc[MISC_B5];
#pragma unroll
        for (int o2 = 0; o2 < 16; o2++) {
            __half2 h = *(__half2*)(smb + OFF_B1 + tid * 80 + o2 * 4);
            float2 f = __half22float2(h);
            s += f.x * misc[MISC_W5 + o2 * 2] + f.y * misc[MISC_W5 + o2 * 2 + 1];
        }
        misc[MISC_RED + tid] = 1.f / (1.f + __expf(-s));
    }
    __syncthreads();
    if (tid < 32) {
        float v = misc[MISC_RED + tid] + misc[MISC_RED + tid + 32] + misc[MISC_RED + tid + 64]
                + ((tid < 4) ? misc[MISC_RED + tid + 96] : 0.f);
#pragma unroll
        for (int off = 16; off; off >>= 1)
            v += __shfl_down_sync(0xffffffffu, v, off);
        if (tid == 0) out[b] = v * (1.f / 100.f);
    }
}

// ---------------------------------------------------------------------------
extern "C" void kernel_launch(void* const* d_in, const int* in_sizes, int n_in,
                              void* d_out, int out_size)
{
    const float* user_emb = (const float*)d_in[0];
    const float* item_emb = (const float*)d_in[1];
    const float* user_scr = (const float*)d_in[2];
    const float* item_scr = (const float*)d_in[3];
    const float* w1 = (const float*)d_in[4];
    const float* b1 = (const float*)d_in[5];
    const float* w2 = (const float*)d_in[6];
    const float* b2 = (const float*)d_in[7];
    const float* w3 = (const float*)d_in[8];
    const float* b3 = (const float*)d_in[9];
    const float* w4 = (const float*)d_in[10];
    const float* b4 = (const float*)d_in[11];
    const float* w5 = (const float*)d_in[12];
    const float* b5 = (const float*)d_in[13];
    const int* user_idx_tensor = (const int*)d_in[14];
    const int* item_idx_tensor = (const int*)d_in[15];
    const int* user_idxs = (const int*)d_in[16];
    const int* item_idxs = (const int*)d_in[17];
    float* out = (float*)d_out;

    pe_kernel<<<(NU + 255) / 256, 256>>>(user_emb, w1, 0, 0, NU);
    pe_kernel<<<(NI + 255) / 256, 256>>>(item_emb, w1, 64, 1, NI);
    scr_cvt_kernel<<<(NU * 14 + 255) / 256, 256>>>(user_scr, 0, NU);
    scr_cvt_kernel<<<(NI * 14 + 255) / 256, 256>>>(item_scr, 1, NI);
    wcvt_kernel<<<29, 256>>>(w2, w3, w4, b2, b3, b4);

    cudaFuncSetAttribute(cnn_main_kernel,
                         cudaFuncAttributeMaxDynamicSharedMemorySize, SMEM_BYTES);
    cnn_main_kernel<<<BB, 256, SMEM_BYTES>>>(
        b1, w5, b5,
        user_idx_tensor, item_idx_tensor, user_idxs, item_idxs,
        out);
}

// round 10
// speedup vs baseline: 1.3981x; 1.0281x over previous
#include <cuda_runtime.h>
#include <cuda_fp16.h>
#include <math.h>
#include <stdint.h>

#define NU 100000
#define NI 50000
#define KN 100
#define BB 8192

// Precomputed fp16 tables
__device__ __half g_pe_user[NU * 64];
__device__ __half g_pe_item[NI * 64];
__device__ __half g_uscr16[(size_t)NU * 112];   // scr rows padded to 112, cols 100-111 zero
__device__ __half g_iscr16[(size_t)NI * 112];
__device__ __half g_w2h[64 * 64];
__device__ __half g_w3h[32 * 64];
__device__ __half g_w4h[32 * 32];
__device__ __half g_b2h[64];
__device__ __half g_b3h[32];
__device__ __half g_b4h[32];

// ---------------------------------------------------------------------------
// Main-kernel SMEM (byte offsets):
//   A1 [112 r][232 k-halves] stride 464B @ 0      (51968)
//      pair p (warps 2p,2p+1; rows 32p..32p+31) owns bytes [p*14848,(p+1)*14848)
//      pair scratch inside own block: H1 @ +0 (32x144), H2 @ +4608 (32x144),
//      H3 @ +9216 (32x80)
//   B1 [224 k][72 n] stride 144B         @ 51968  (32256)  never overwritten
//   W2 [64][72h]  stride 144             @ 84224  (9216)
//   W3 [32][72h]  stride 144             @ 93440  (4608)
//   W4 [32][40h]  stride 80              @ 98048  (2560)
//   MISC (floats)                        @ 100608
// ---------------------------------------------------------------------------
#define OFF_A1   0
#define OFF_B1   51968
#define OFF_W2   84224
#define OFF_W3   93440
#define OFF_W4   98048
#define OFF_MISC 100608
#define SMEM_BYTES 102464
#define H1OFF 0
#define H2OFF 4608
#define H3OFF 9216
// MISC float indices
#define MISC_W5   0
#define MISC_B5   32
#define MISC_RED0 36
#define MISC_RED1 148
#define MISC_NIDX 260

#define CP_ASYNC16(dst, src) \
    asm volatile("cp.async.cg.shared.global [%0], [%1], 16;" :: "r"(dst), "l"(src))
#define CP_COMMIT() asm volatile("cp.async.commit_group;" ::: "memory")
#define CP_WAIT0()  asm volatile("cp.async.wait_group 0;" ::: "memory")
#define BAR64(id)   asm volatile("bar.sync %0, 64;" :: "r"(id) : "memory")

__device__ __forceinline__ void ldsm4(uint32_t (&r)[4], uint32_t a) {
    asm volatile("ldmatrix.sync.aligned.m8n8.x4.shared.b16 {%0,%1,%2,%3}, [%4];"
                 : "=r"(r[0]), "=r"(r[1]), "=r"(r[2]), "=r"(r[3]) : "r"(a));
}
__device__ __forceinline__ void ldsm2(uint32_t (&r)[2], uint32_t a) {
    asm volatile("ldmatrix.sync.aligned.m8n8.x2.shared.b16 {%0,%1}, [%2];"
                 : "=r"(r[0]), "=r"(r[1]) : "r"(a));
}
__device__ __forceinline__ void ldsm2t(uint32_t (&r)[2], uint32_t a) {
    asm volatile("ldmatrix.sync.aligned.m8n8.x2.trans.shared.b16 {%0,%1}, [%2];"
                 : "=r"(r[0]), "=r"(r[1]) : "r"(a));
}
__device__ __forceinline__ void mma_f32acc(float (&c)[4], const uint32_t (&a)[4],
                                           const uint32_t (&b)[2]) {
    asm volatile(
        "mma.sync.aligned.m16n8k16.row.col.f32.f16.f16.f32 "
        "{%0,%1,%2,%3}, {%4,%5,%6,%7}, {%8,%9}, {%0,%1,%2,%3};"
        : "+f"(c[0]), "+f"(c[1]), "+f"(c[2]), "+f"(c[3])
        : "r"(a[0]), "r"(a[1]), "r"(a[2]), "r"(a[3]), "r"(b[0]), "r"(b[1]));
}
__device__ __forceinline__ void mma_f16acc(uint32_t (&c)[2], const uint32_t (&a)[4],
                                           const uint32_t (&b)[2]) {
    asm volatile(
        "mma.sync.aligned.m16n8k16.row.col.f16.f16.f16.f16 "
        "{%0,%1}, {%2,%3,%4,%5}, {%6,%7}, {%0,%1};"
        : "+r"(c[0]), "+r"(c[1])
        : "r"(a[0]), "r"(a[1]), "r"(a[2]), "r"(a[3]), "r"(b[0]), "r"(b[1]));
}

__device__ __forceinline__ uint32_t h2_bits(float x, float y) {
    __half2 h = __floats2half2_rn(x, y);
    return *(uint32_t*)&h;
}
__device__ __forceinline__ void cvt_store4(char* dst, float4 v) {
    uint32_t lo = h2_bits(v.x, v.y), hi = h2_bits(v.z, v.w);
    uint2 u; u.x = lo; u.y = hi;
    *(uint2*)dst = u;
}

// ---------------------------------------------------------------------------
// Fused preprocessing kernel: block-range dispatch.
//   [0, PEU)            : pe user   (256 rows/block, tensor core)
//   [PEU, PEU+PEI)      : pe item
//   [.., +SCRU)         : scr_cvt user (1 chunk/thread)
//   [.., +SCRI)         : scr_cvt item
//   last block          : weight/bias conversion
// ---------------------------------------------------------------------------
#define PEU_BLOCKS  ((NU + 255) / 256)          // 391
#define PEI_BLOCKS  ((NI + 255) / 256)          // 196
#define SCRU_BLOCKS ((NU * 14 + 255) / 256)     // 5469
#define SCRI_BLOCKS ((NI * 14 + 255) / 256)     // 2735
#define PRE_BLOCKS  (PEU_BLOCKS + PEI_BLOCKS + SCRU_BLOCKS + SCRI_BLOCKS + 1)

__device__ __forceinline__ void pe_block(
    const float* __restrict__ emb, const float* __restrict__ w1,
    int w1_off, __half* __restrict__ pe, int nrows, int rows0,
    __half* W1h, __half* E, int tid)
{
    for (int t = tid; t < 64 * 16; t += 256) {
        int o = t >> 4, k4 = t & 15;
        float4 v = *(const float4*)(w1 + o * 128 + w1_off + k4 * 4);
        cvt_store4((char*)(W1h + o * 72 + k4 * 4), v);
    }
    for (int t = tid; t < 256 * 16; t += 256) {
        int r = t >> 4, k4 = t & 15;
        int n = rows0 + r;
        float4 v = (n < nrows) ? *(const float4*)(emb + (size_t)n * 64 + k4 * 4)
                               : make_float4(0.f, 0.f, 0.f, 0.f);
        cvt_store4((char*)(E + r * 72 + k4 * 4), v);
    }
    __syncthreads();

    const int lane = tid & 31, w = tid >> 5;
    uint32_t sE = (uint32_t)__cvta_generic_to_shared(E);
    uint32_t sW = (uint32_t)__cvta_generic_to_shared(W1h);
    uint32_t aAddr[2];
#pragma unroll
    for (int mt = 0; mt < 2; mt++)
        aAddr[mt] = sE + (uint32_t)(w * 32 + mt * 16 + (lane & 15)) * 144u
                  + (uint32_t)((lane >> 4) << 4);
    uint32_t bAddr0 = sW + (uint32_t)(lane & 7) * 144u + (uint32_t)(((lane >> 3) & 1) << 4);

    float acc[2][8][4];
#pragma unroll
    for (int mt = 0; mt < 2; mt++)
#pragma unroll
        for (int nt = 0; nt < 8; nt++)
#pragma unroll
            for (int i = 0; i < 4; i++) acc[mt][nt][i] = 0.f;

#pragma unroll
    for (int ks = 0; ks < 4; ks++) {
        uint32_t a[2][4];
        ldsm4(a[0], aAddr[0] + ks * 32);
        ldsm4(a[1], aAddr[1] + ks * 32);
#pragma unroll
        for (int nt = 0; nt < 8; nt++) {
            uint32_t b[2];
            ldsm2(b, bAddr0 + (uint32_t)nt * 8u * 144u + ks * 32);
            mma_f32acc(acc[0][nt], a[0], b);
            mma_f32acc(acc[1][nt], a[1], b);
        }
    }

    int c0 = (lane & 3) * 2;
#pragma unroll
    for (int mt = 0; mt < 2; mt++) {
        int r0 = rows0 + w * 32 + mt * 16 + (lane >> 2);
#pragma unroll
        for (int nt = 0; nt < 8; nt++) {
            int col = nt * 8 + c0;
            if (r0 < nrows)
                *(__half2*)(pe + (size_t)r0 * 64 + col) =
                    __floats2half2_rn(acc[mt][nt][0], acc[mt][nt][1]);
            if (r0 + 8 < nrows)
                *(__half2*)(pe + (size_t)(r0 + 8) * 64 + col) =
                    __floats2half2_rn(acc[mt][nt][2], acc[mt][nt][3]);
        }
    }
}

__device__ __forceinline__ void scr_chunk(
    const float* __restrict__ src, __half* __restrict__ dst, int nrows, int t)
{
    if (t >= nrows * 14) return;
    int n = t / 14, cb = t % 14;
    uint32_t o[4] = {0, 0, 0, 0};
    if (cb < 12) {
        float4 a = *(const float4*)(src + (size_t)n * 100 + cb * 8);
        float4 bq = *(const float4*)(src + (size_t)n * 100 + cb * 8 + 4);
        o[0] = h2_bits(a.x, a.y);  o[1] = h2_bits(a.z, a.w);
        o[2] = h2_bits(bq.x, bq.y); o[3] = h2_bits(bq.z, bq.w);
    } else if (cb == 12) {
        float4 a = *(const float4*)(src + (size_t)n * 100 + 96);
        o[0] = h2_bits(a.x, a.y);  o[1] = h2_bits(a.z, a.w);
    }
    uint4 v; v.x = o[0]; v.y = o[1]; v.z = o[2]; v.w = o[3];
    *(uint4*)(dst + (size_t)n * 112 + cb * 8) = v;
}

__global__ __launch_bounds__(256) void pre_kernel(
    const float* __restrict__ user_emb, const float* __restrict__ item_emb,
    const float* __restrict__ user_scr, const float* __restrict__ item_scr,
    const float* __restrict__ w1, const float* __restrict__ w2,
    const float* __restrict__ w3, const float* __restrict__ w4,
    const float* __restrict__ b2, const float* __restrict__ b3,
    const float* __restrict__ b4)
{
    __shared__ __half W1h[64 * 72];
    __shared__ __half E[256 * 72];
    const int bid = blockIdx.x, tid = threadIdx.x;

    if (bid < PEU_BLOCKS) {
        pe_block(user_emb, w1, 0, g_pe_user, NU, bid * 256, W1h, E, tid);
    } else if (bid < PEU_BLOCKS + PEI_BLOCKS) {
        pe_block(item_emb, w1, 64, g_pe_item, NI, (bid - PEU_BLOCKS) * 256, W1h, E, tid);
    } else if (bid < PEU_BLOCKS + PEI_BLOCKS + SCRU_BLOCKS) {
        scr_chunk(user_scr, g_uscr16, NU,
                  (bid - PEU_BLOCKS - PEI_BLOCKS) * 256 + tid);
    } else if (bid < PEU_BLOCKS + PEI_BLOCKS + SCRU_BLOCKS + SCRI_BLOCKS) {
        scr_chunk(item_scr, g_iscr16, NI,
                  (bid - PEU_BLOCKS - PEI_BLOCKS - SCRU_BLOCKS) * 256 + tid);
    } else {
        for (int t = tid; t < 7296; t += 256) {
            if (t < 4096) g_w2h[t] = __float2half_rn(w2[t]);
            else if (t < 6144) g_w3h[t - 4096] = __float2half_rn(w3[t - 4096]);
            else if (t < 7168) g_w4h[t - 6144] = __float2half_rn(w4[t - 6144]);
            else if (t < 7232) g_b2h[t - 7168] = __float2half_rn(b2[t - 7168]);
            else if (t < 7264) g_b3h[t - 7232] = __float2half_rn(b3[t - 7232]);
            else g_b4h[t - 7264] = __float2half_rn(b4[t - 7264]);
        }
    }
}

// ---------------------------------------------------------------------------
__global__ __launch_bounds__(256, 2) void cnn_main_kernel(
    const float* __restrict__ b1g,
    const float* __restrict__ w5g, const float* __restrict__ b5g,
    const int* __restrict__ uidxT, const int* __restrict__ iidxT,
    const int* __restrict__ uidxs, const int* __restrict__ iidxs,
    float* __restrict__ out)
{
    extern __shared__ char smb[];
    float* misc = (float*)(smb + OFF_MISC);
    int* nidx = (int*)(misc + MISC_NIDX);
    uint32_t sbase = (uint32_t)__cvta_generic_to_shared(smb);
    const int tid = threadIdx.x;
    const int b = blockIdx.x;

    // Phase 0: neighbor indices, w5/b5, zero B1 pad rows (k 100-111, 212-223)
    if (tid < 200) {
        nidx[tid] = (tid < 100) ? uidxT[(size_t)uidxs[b] * KN + tid]
                                : iidxT[(size_t)iidxs[b] * KN + (tid - 100)];
    } else if (tid < 232) {
        misc[MISC_W5 + tid - 200] = w5g[tid - 200];
    } else if (tid == 232) {
        misc[MISC_B5] = b5g[0];
    }
    if (tid < 192) {
        int rr = tid >> 3;
        int row = (rr < 12) ? 100 + rr : 200 + rr;
        *(uint4*)(smb + OFF_B1 + row * 144 + (tid & 7) * 16) = make_uint4(0, 0, 0, 0);
    }
    __syncthreads();

    // Phase 1: all gathers via cp.async (16B chunks)
    for (int t = tid; t < 2800; t += 256) {
        int r = t / 28, c = t % 28;
        const char* src = (c < 14)
            ? (const char*)(g_uscr16 + (size_t)nidx[r] * 112) + c * 16
            : (const char*)(g_iscr16 + (size_t)nidx[100 + r] * 112) + (c - 14) * 16;
        CP_ASYNC16(sbase + OFF_A1 + (uint32_t)(r * 464 + c * 16), src);
    }
    for (int t = tid; t < 1600; t += 256) {
        int j = t >> 3, c = t & 7;
        const char* src = (j < 100)
            ? (const char*)(g_pe_user + (size_t)nidx[j] * 64) + c * 16
            : (const char*)(g_pe_item + (size_t)nidx[j] * 64) + c * 16;
        int dr = (j < 100) ? j : j + 12;
        CP_ASYNC16(sbase + OFF_B1 + (uint32_t)(dr * 144 + c * 16), src);
    }
    for (int t = tid; t < 512; t += 256) {
        int o = t >> 3, c = t & 7;
        CP_ASYNC16(sbase + OFF_W2 + (uint32_t)(o * 144 + c * 16),
                   (const char*)(g_w2h + o * 64 + c * 8));
    }
    if (tid < 256) {
        int o = tid >> 3, c = tid & 7;
        CP_ASYNC16(sbase + OFF_W3 + (uint32_t)(o * 144 + c * 16),
                   (const char*)(g_w3h + o * 64 + c * 8));
    }
    if (tid < 128) {
        int o = tid >> 2, c = tid & 3;
        CP_ASYNC16(sbase + OFF_W4 + (uint32_t)(o * 80 + c * 16),
                   (const char*)(g_w4h + o * 32 + c * 8));
    }
    CP_COMMIT();
    CP_WAIT0();
    __syncthreads();   // block sync #1: all tiles resident

    const int lane = tid & 31, w = tid >> 5;
    const int mw = w >> 1, nw = w & 1;
    const int mtn = (mw == 3) ? 1 : 2;
    const int cc = (lane & 3) * 2;
    const int r = lane >> 2;
    const int pbar = mw + 1;                 // named barrier per pair, 64 threads
    const int poff = OFF_A1 + mw * 14848;    // pair-private scratch (own A1 rows)

    // ---- GEMM1 (fp32 acc): rows mw*32.., cols nw*32.., K=224 (14 k16 steps)
    {
        float2 bfrag[4];
#pragma unroll
        for (int nt = 0; nt < 4; nt++)
            bfrag[nt] = *(const float2*)(b1g + nw * 32 + nt * 8 + cc);

        uint32_t aAddr[2];
#pragma unroll
        for (int mt = 0; mt < 2; mt++)
            aAddr[mt] = sbase + OFF_A1
                      + (uint32_t)(mw * 32 + mt * 16 + (lane & 15)) * 464u
                      + (uint32_t)((lane >> 4) << 4);
        uint32_t bAddr[4];
#pragma unroll
        for (int nt = 0; nt < 4; nt++)
            bAddr[nt] = sbase + OFF_B1 + (uint32_t)(lane & 15) * 144u
                      + (uint32_t)((nw * 4 + nt) << 4);

        float acc[2][4][4];
#pragma unroll
        for (int mt = 0; mt < 2; mt++)
#pragma unroll
            for (int nt = 0; nt < 4; nt++)
#pragma unroll
                for (int i = 0; i < 4; i++) acc[mt][nt][i] = 0.f;

#pragma unroll
        for (int ks = 0; ks < 14; ks++) {
            uint32_t bq[4][2];
#pragma unroll
            for (int nt = 0; nt < 4; nt++) ldsm2t(bq[nt], bAddr[nt] + ks * 2304);
#pragma unroll
            for (int mt = 0; mt < 2; mt++) {
                if (mt < mtn) {
                    uint32_t a[4];
                    ldsm4(a, aAddr[mt] + ks * 32);
#pragma unroll
                    for (int nt = 0; nt < 4; nt++) mma_f32acc(acc[mt][nt], a, bq[nt]);
                }
            }
        }
        BAR64(pbar);   // pair: partner done reading its A rows before H1 overwrite

#pragma unroll
        for (int mt = 0; mt < 2; mt++) {
            if (mt < mtn) {
                int lrow = mt * 16 + r;
#pragma unroll
                for (int nt = 0; nt < 4; nt++) {
                    int col = nw * 32 + nt * 8 + cc;
                    *(uint32_t*)(smb + poff + H1OFF + lrow * 144 + col * 2) =
                        h2_bits(fmaxf(acc[mt][nt][0] + bfrag[nt].x, 0.f),
                                fmaxf(acc[mt][nt][1] + bfrag[nt].y, 0.f));
                    *(uint32_t*)(smb + poff + H1OFF + (lrow + 8) * 144 + col * 2) =
                        h2_bits(fmaxf(acc[mt][nt][2] + bfrag[nt].x, 0.f),
                                fmaxf(acc[mt][nt][3] + bfrag[nt].y, 0.f));
                }
            }
        }
    }
    BAR64(pbar);   // pair: H1 complete

    // ---- L2 (f16 acc): K=64, N=64; H1 -> H2 (pair scratch)
    {
        __half2 bias2[4];
#pragma unroll
        for (int nt = 0; nt < 4; nt++)
            bias2[nt] = *(const __half2*)(g_b2h + nw * 32 + nt * 8 + cc);

        uint32_t aA = sbase + poff + H1OFF + (uint32_t)(lane & 15) * 144u
                    + (uint32_t)((lane >> 4) << 4);
        uint32_t bAddr[4];
#pragma unroll
        for (int nt = 0; nt < 4; nt++)
            bAddr[nt] = sbase + OFF_W2 + (uint32_t)(nw * 32 + nt * 8 + (lane & 7)) * 144u
                      + (uint32_t)(((lane >> 3) & 1) << 4);

        uint32_t acc[2][4][2];
#pragma unroll
        for (int mt = 0; mt < 2; mt++)
#pragma unroll
            for (int nt = 0; nt < 4; nt++) { acc[mt][nt][0] = 0u; acc[mt][nt][1] = 0u; }

#pragma unroll
        for (int ks = 0; ks < 4; ks++) {
            uint32_t bq[4][2];
#pragma unroll
            for (int nt = 0; nt < 4; nt++) ldsm2(bq[nt], bAddr[nt] + ks * 32);
#pragma unroll
            for (int mt = 0; mt < 2; mt++) {
                if (mt < mtn) {
                    uint32_t a[4];
                    ldsm4(a, aA + mt * 2304 + ks * 32);
#pragma unroll
                    for (int nt = 0; nt < 4; nt++) mma_f16acc(acc[mt][nt], a, bq[nt]);
                }
            }
        }

        const __half2 z = __floats2half2_rn(0.f, 0.f);
#pragma unroll
        for (int mt = 0; mt < 2; mt++) {
            if (mt < mtn) {
                int lrow = mt * 16 + r;
#pragma unroll
                for (int nt = 0; nt < 4; nt++) {
                    int col = nw * 32 + nt * 8 + cc;
                    __half2 v0 = __hmax2(__hadd2(*(__half2*)&acc[mt][nt][0], bias2[nt]), z);
                    __half2 v1 = __hmax2(__hadd2(*(__half2*)&acc[mt][nt][1], bias2[nt]), z);
                    *(uint32_t*)(smb + poff + H2OFF + lrow * 144 + col * 2) = *(uint32_t*)&v0;
                    *(uint32_t*)(smb + poff + H2OFF + (lrow + 8) * 144 + col * 2) = *(uint32_t*)&v1;
                }
            }
        }
    }
    BAR64(pbar);   // pair: H2 complete

    // ---- L3 (f16 acc): K=64, N=32; H2 -> H3 (stride 80)
    {
        __half2 bias2[2];
#pragma unroll
        for (int nt = 0; nt < 2; nt++)
            bias2[nt] = *(const __half2*)(g_b3h + nw * 16 + nt * 8 + cc);

        uint32_t aA = sbase + poff + H2OFF + (uint32_t)(lane & 15) * 144u
                    + (uint32_t)((lane >> 4) << 4);
        uint32_t bAddr[2];
#pragma unroll
        for (int nt = 0; nt < 2; nt++)
            bAddr[nt] = sbase + OFF_W3 + (uint32_t)(nw * 16 + nt * 8 + (lane & 7)) * 144u
                      + (uint32_t)(((lane >> 3) & 1) << 4);

        uint32_t acc[2][2][2];
#pragma unroll
        for (int mt = 0; mt < 2; mt++)
#pragma unroll
            for (int nt = 0; nt < 2; nt++) { acc[mt][nt][0] = 0u; acc[mt][nt][1] = 0u; }

#pragma unroll
        for (int ks = 0; ks < 4; ks++) {
            uint32_t bq[2][2];
#pragma unroll
            for (int nt = 0; nt < 2; nt++) ldsm2(bq[nt], bAddr[nt] + ks * 32);
#pragma unroll
            for (int mt = 0; mt < 2; mt++) {
                if (mt < mtn) {
                    uint32_t a[4];
                    ldsm4(a, aA + mt * 2304 + ks * 32);
#pragma unroll
                    for (int nt = 0; nt < 2; nt++) mma_f16acc(acc[mt][nt], a, bq[nt]);
                }
            }
        }

        const __half2 z = __floats2half2_rn(0.f, 0.f);
#pragma unroll
        for (int mt = 0; mt < 2; mt++) {
            if (mt < mtn) {
                int lrow = mt * 16 + r;
#pragma unroll
                for (int nt = 0; nt < 2; nt++) {
                    int col = nw * 16 + nt * 8 + cc;
                    __half2 v0 = __hmax2(__hadd2(*(__half2*)&acc[mt][nt][0], bias2[nt]), z);
                    __half2 v1 = __hmax2(__hadd2(*(__half2*)&acc[mt][nt][1], bias2[nt]), z);
                    *(uint32_t*)(smb + poff + H3OFF + lrow * 80 + col * 2) = *(uint32_t*)&v0;
                    *(uint32_t*)(smb + poff + H3OFF + (lrow + 8) * 80 + col * 2) = *(uint32_t*)&v1;
                }
            }
        }
    }
    BAR64(pbar);   // pair: H3 complete

    // ---- L4 (f16 acc, K=32, N=32) in registers + L5 dot with w5 ----
    {
        __half2 bias2[2];
        float w5f[2][2];
#pragma unroll
        for (int nt = 0; nt < 2; nt++) {
            int col = nw * 16 + nt * 8 + cc;
            bias2[nt] = *(const __half2*)(g_b4h + col);
            w5f[nt][0] = misc[MISC_W5 + col];
            w5f[nt][1] = misc[MISC_W5 + col + 1];
        }

        uint32_t aA = sbase + poff + H3OFF + (uint32_t)(lane & 15) * 80u
                    + (uint32_t)((lane >> 4) << 4);
        uint32_t bAddr[2];
#pragma unroll
        for (int nt = 0; nt < 2; nt++)
            bAddr[nt] = sbase + OFF_W4 + (uint32_t)(nw * 16 + nt * 8 + (lane & 7)) * 80u
                      + (uint32_t)(((lane >> 3) & 1) << 4);

        uint32_t acc[2][2][2];
#pragma unroll
        for (int mt = 0; mt < 2; mt++)
#pragma unroll
            for (int nt = 0; nt < 2; nt++) { acc[mt][nt][0] = 0u; acc[mt][nt][1] = 0u; }

#pragma unroll
        for (int ks = 0; ks < 2; ks++) {
            uint32_t bq[2][2];
#pragma unroll
            for (int nt = 0; nt < 2; nt++) ldsm2(bq[nt], bAddr[nt] + ks * 32);
#pragma unroll
            for (int mt = 0; mt < 2; mt++) {
                if (mt < mtn) {
                    uint32_t a[4];
                    ldsm4(a, aA + mt * 1280 + ks * 32);
#pragma unroll
                    for (int nt = 0; nt < 2; nt++) mma_f16acc(acc[mt][nt], a, bq[nt]);
                }
            }
        }

        const __half2 z = __floats2half2_rn(0.f, 0.f);
        float* RED = misc + (nw ? MISC_RED1 : MISC_RED0);
#pragma unroll
        for (int mt = 0; mt < 2; mt++) {
            if (mt < mtn) {
                float s0 = 0.f, s1 = 0.f;
#pragma unroll
                for (int nt = 0; nt < 2; nt++) {
                    __half2 h0 = __hmax2(__hadd2(*(__half2*)&acc[mt][nt][0], bias2[nt]), z);
                    __half2 h1 = __hmax2(__hadd2(*(__half2*)&acc[mt][nt][1], bias2[nt]), z);
                    float2 f0 = __half22float2(h0);
                    float2 f1 = __half22float2(h1);
                    s0 += f0.x * w5f[nt][0] + f0.y * w5f[nt][1];
                    s1 += f1.x * w5f[nt][0] + f1.y * w5f[nt][1];
                }
                s0 += __shfl_xor_sync(0xffffffffu, s0, 1);
                s0 += __shfl_xor_sync(0xffffffffu, s0, 2);
                s1 += __shfl_xor_sync(0xffffffffu, s1, 1);
                s1 += __shfl_xor_sync(0xffffffffu, s1, 2);
                if ((lane & 3) == 0) {
                    int row = mw * 32 + mt * 16 + r;
                    RED[row] = s0;
                    RED[row + 8] = s1;
                }
            }
        }
    }
    __syncthreads();   // block sync #2: all RED partials done

    // L5: sigmoid(s + b5), then mean over rows 0-99
    if (tid < 100) {
        float s = misc[MISC_RED0 + tid] + misc[MISC_RED1 + tid] + misc[MISC_B5];
        misc[MISC_RED0 + tid] = 1.f / (1.f + __expf(-s));
    }
    __syncthreads();
    if (tid < 32) {
        float v = misc[MISC_RED0 + tid] + misc[MISC_RED0 + tid + 32]
                + misc[MISC_RED0 + tid + 64]
                + ((tid < 4) ? misc[MISC_RED0 + tid + 96] : 0.f);
#pragma unroll
        for (int off = 16; off; off >>= 1)
            v += __shfl_down_sync(0xffffffffu, v, off);
        if (tid == 0) out[b] = v * (1.f / 100.f);
    }
}

// ---------------------------------------------------------------------------
extern "C" void kernel_launch(void* const* d_in, const int* in_sizes, int n_in,
                              void* d_out, int out_size)
{
    const float* user_emb = (const float*)d_in[0];
    const float* item_emb = (const float*)d_in[1];
    const float* user_scr = (const float*)d_in[2];
    const float* item_scr = (const float*)d_in[3];
    const float* w1 = (const float*)d_in[4];
    const float* b1 = (const float*)d_in[5];
    const float* w2 = (const float*)d_in[6];
    const float* b2 = (const float*)d_in[7];
    const float* w3 = (const float*)d_in[8];
    const float* b3 = (const float*)d_in[9];
    const float* w4 = (const float*)d_in[10];
    const float* b4 = (const float*)d_in[11];
    const float* w5 = (const float*)d_in[12];
    const float* b5 = (const float*)d_in[13];
    const int* user_idx_tensor = (const int*)d_in[14];
    const int* item_idx_tensor = (const int*)d_in[15];
    const int* user_idxs = (const int*)d_in[16];
    const int* item_idxs = (const int*)d_in[17];
    float* out = (float*)d_out;

    pre_kernel<<<PRE_BLOCKS, 256>>>(user_emb, item_emb, user_scr, item_scr,
                                    w1, w2, w3, w4, b2, b3, b4);

    cudaFuncSetAttribute(cnn_main_kernel,
                         cudaFuncAttributeMaxDynamicSharedMemorySize, SMEM_BYTES);
    cnn_main_kernel<<<BB, 256, SMEM_BYTES>>>(
        b1, w5, b5,
        user_idx_tensor, item_idx_tensor, user_idxs, item_idxs,
        out);
}

// round 11
// speedup vs baseline: 1.6608x; 1.1879x over previous
#include <cuda_runtime.h>
#include <cuda_fp16.h>
#include <math.h>
#include <stdint.h>

#define NU 100000
#define NI 50000
#define KN 100
#define BB 8192

// Precomputed fp16 tables
__device__ __half g_pe_user[NU * 64];
__device__ __half g_pe_item[NI * 64];
__device__ __half g_uscr16[(size_t)NU * 112];   // scr rows padded to 112, cols 100-111 zero
__device__ __half g_iscr16[(size_t)NI * 112];
__device__ __half g_w2h[64 * 64];
__device__ __half g_w3h[32 * 64];
__device__ __half g_w4h[32 * 32];
__device__ __half g_b2h[64];
__device__ __half g_b3h[32];
__device__ __half g_b4h[32];

// ---------------------------------------------------------------------------
// Main-kernel SMEM (byte offsets), 3 CTAs/SM target (~74KB):
//   ABUF [112 r][120 k-halves] stride 240B @ 0      (26880)
//        pass 1: user scr half (K 0-111); pass 2 (pair-local reload): item half
//        after GEMM1: pair p's H2 scratch @ p*7680 (32x144=4608)
//   B1  [224 k][64 n-halves] stride 128B, XOR-swizzled @ 26880 (28672)
//        chunk c at byte ((c ^ (row&7))<<4); rows 100-111/212-223 zero
//        after GEMM1: pair p slice @ +p*7168: H1 @+0 (32x144), H3 @+4608 (32x80)
//   W2 [64][72h]  stride 144  @ 55552 (9216)
//   W3 [32][72h]  stride 144  @ 64768 (4608)
//   W4 [32][40h]  stride 80   @ 69376 (2560)
//   MISC (floats)             @ 71936 (1840)
// Total 73792 B -> 3 CTAs/SM
// ---------------------------------------------------------------------------
#define OFF_AB   0
#define OFF_B1   26880
#define OFF_W2   55552
#define OFF_W3   64768
#define OFF_W4   69376
#define OFF_MISC 71936
#define SMEM_BYTES 73792
// MISC float indices
#define MISC_W5   0
#define MISC_B5   32
#define MISC_RED0 36
#define MISC_RED1 148
#define MISC_NIDX 260

#define CP_ASYNC16(dst, src) \
    asm volatile("cp.async.cg.shared.global [%0], [%1], 16;" :: "r"(dst), "l"(src))
#define CP_COMMIT() asm volatile("cp.async.commit_group;" ::: "memory")
#define CP_WAIT0()  asm volatile("cp.async.wait_group 0;" ::: "memory")
#define BAR64(id)   asm volatile("bar.sync %0, 64;" :: "r"(id) : "memory")

__device__ __forceinline__ void ldsm4(uint32_t (&r)[4], uint32_t a) {
    asm volatile("ldmatrix.sync.aligned.m8n8.x4.shared.b16 {%0,%1,%2,%3}, [%4];"
                 : "=r"(r[0]), "=r"(r[1]), "=r"(r[2]), "=r"(r[3]) : "r"(a));
}
__device__ __forceinline__ void ldsm2(uint32_t (&r)[2], uint32_t a) {
    asm volatile("ldmatrix.sync.aligned.m8n8.x2.shared.b16 {%0,%1}, [%2];"
                 : "=r"(r[0]), "=r"(r[1]) : "r"(a));
}
__device__ __forceinline__ void ldsm2t(uint32_t (&r)[2], uint32_t a) {
    asm volatile("ldmatrix.sync.aligned.m8n8.x2.trans.shared.b16 {%0,%1}, [%2];"
                 : "=r"(r[0]), "=r"(r[1]) : "r"(a));
}
__device__ __forceinline__ void mma_f32acc(float (&c)[4], const uint32_t (&a)[4],
                                           const uint32_t (&b)[2]) {
    asm volatile(
        "mma.sync.aligned.m16n8k16.row.col.f32.f16.f16.f32 "
        "{%0,%1,%2,%3}, {%4,%5,%6,%7}, {%8,%9}, {%0,%1,%2,%3};"
        : "+f"(c[0]), "+f"(c[1]), "+f"(c[2]), "+f"(c[3])
        : "r"(a[0]), "r"(a[1]), "r"(a[2]), "r"(a[3]), "r"(b[0]), "r"(b[1]));
}
__device__ __forceinline__ void mma_f16acc(uint32_t (&c)[2], const uint32_t (&a)[4],
                                           const uint32_t (&b)[2]) {
    asm volatile(
        "mma.sync.aligned.m16n8k16.row.col.f16.f16.f16.f16 "
        "{%0,%1}, {%2,%3,%4,%5}, {%6,%7}, {%0,%1};"
        : "+r"(c[0]), "+r"(c[1])
        : "r"(a[0]), "r"(a[1]), "r"(a[2]), "r"(a[3]), "r"(b[0]), "r"(b[1]));
}

__device__ __forceinline__ uint32_t h2_bits(float x, float y) {
    __half2 h = __floats2half2_rn(x, y);
    return *(uint32_t*)&h;
}
__device__ __forceinline__ void cvt_store4(char* dst, float4 v) {
    uint32_t lo = h2_bits(v.x, v.y), hi = h2_bits(v.z, v.w);
    uint2 u; u.x = lo; u.y = hi;
    *(uint2*)dst = u;
}

// ---------------------------------------------------------------------------
// Fused preprocessing kernel: block-range dispatch.
// ---------------------------------------------------------------------------
#define PEU_BLOCKS  ((NU + 255) / 256)
#define PEI_BLOCKS  ((NI + 255) / 256)
#define SCR_CPB     2048
#define SCRU_BLOCKS ((NU * 14 + SCR_CPB - 1) / SCR_CPB)
#define SCRI_BLOCKS ((NI * 14 + SCR_CPB - 1) / SCR_CPB)
#define PRE_BLOCKS  (PEU_BLOCKS + PEI_BLOCKS + SCRU_BLOCKS + SCRI_BLOCKS + 1)

__device__ __forceinline__ void pe_block(
    const float* __restrict__ emb, const float* __restrict__ w1,
    int w1_off, __half* __restrict__ pe, int nrows, int rows0,
    __half* W1h, __half* E, int tid)
{
    for (int t = tid; t < 64 * 16; t += 256) {
        int o = t >> 4, k4 = t & 15;
        float4 v = *(const float4*)(w1 + o * 128 + w1_off + k4 * 4);
        cvt_store4((char*)(W1h + o * 72 + k4 * 4), v);
    }
    for (int t = tid; t < 256 * 16; t += 256) {
        int r = t >> 4, k4 = t & 15;
        int n = rows0 + r;
        float4 v = (n < nrows) ? *(const float4*)(emb + (size_t)n * 64 + k4 * 4)
                               : make_float4(0.f, 0.f, 0.f, 0.f);
        cvt_store4((char*)(E + r * 72 + k4 * 4), v);
    }
    __syncthreads();

    const int lane = tid & 31, w = tid >> 5;
    uint32_t sE = (uint32_t)__cvta_generic_to_shared(E);
    uint32_t sW = (uint32_t)__cvta_generic_to_shared(W1h);
    uint32_t aAddr[2];
#pragma unroll
    for (int mt = 0; mt < 2; mt++)
        aAddr[mt] = sE + (uint32_t)(w * 32 + mt * 16 + (lane & 15)) * 144u
                  + (uint32_t)((lane >> 4) << 4);
    uint32_t bAddr0 = sW + (uint32_t)(lane & 7) * 144u + (uint32_t)(((lane >> 3) & 1) << 4);

    float acc[2][8][4];
#pragma unroll
    for (int mt = 0; mt < 2; mt++)
#pragma unroll
        for (int nt = 0; nt < 8; nt++)
#pragma unroll
            for (int i = 0; i < 4; i++) acc[mt][nt][i] = 0.f;

#pragma unroll
    for (int ks = 0; ks < 4; ks++) {
        uint32_t a[2][4];
        ldsm4(a[0], aAddr[0] + ks * 32);
        ldsm4(a[1], aAddr[1] + ks * 32);
#pragma unroll
        for (int nt = 0; nt < 8; nt++) {
            uint32_t b[2];
            ldsm2(b, bAddr0 + (uint32_t)nt * 8u * 144u + ks * 32);
            mma_f32acc(acc[0][nt], a[0], b);
            mma_f32acc(acc[1][nt], a[1], b);
        }
    }

    int c0 = (lane & 3) * 2;
#pragma unroll
    for (int mt = 0; mt < 2; mt++) {
        int r0 = rows0 + w * 32 + mt * 16 + (lane >> 2);
#pragma unroll
        for (int nt = 0; nt < 8; nt++) {
            int col = nt * 8 + c0;
            if (r0 < nrows)
                *(__half2*)(pe + (size_t)r0 * 64 + col) =
                    __floats2half2_rn(acc[mt][nt][0], acc[mt][nt][1]);
            if (r0 + 8 < nrows)
                *(__half2*)(pe + (size_t)(r0 + 8) * 64 + col) =
                    __floats2half2_rn(acc[mt][nt][2], acc[mt][nt][3]);
        }
    }
}

__device__ __forceinline__ void scr_chunk(
    const float* __restrict__ src, __half* __restrict__ dst, int nrows, int t)
{
    if (t >= nrows * 14) return;
    int n = t / 14, cb = t % 14;
    uint32_t o[4] = {0, 0, 0, 0};
    if (cb < 12) {
        float4 a = *(const float4*)(src + (size_t)n * 100 + cb * 8);
        float4 bq = *(const float4*)(src + (size_t)n * 100 + cb * 8 + 4);
        o[0] = h2_bits(a.x, a.y);  o[1] = h2_bits(a.z, a.w);
        o[2] = h2_bits(bq.x, bq.y); o[3] = h2_bits(bq.z, bq.w);
    } else if (cb == 12) {
        float4 a = *(const float4*)(src + (size_t)n * 100 + 96);
        o[0] = h2_bits(a.x, a.y);  o[1] = h2_bits(a.z, a.w);
    }
    uint4 v; v.x = o[0]; v.y = o[1]; v.z = o[2]; v.w = o[3];
    *(uint4*)(dst + (size_t)n * 112 + cb * 8) = v;
}

__global__ __launch_bounds__(256) void pre_kernel(
    const float* __restrict__ user_emb, const float* __restrict__ item_emb,
    const float* __restrict__ user_scr, const float* __restrict__ item_scr,
    const float* __restrict__ w1, const float* __restrict__ w2,
    const float* __restrict__ w3, const float* __restrict__ w4,
    const float* __restrict__ b2, const float* __restrict__ b3,
    const float* __restrict__ b4)
{
    __shared__ __half W1h[64 * 72];
    __shared__ __half E[256 * 72];
    const int bid = blockIdx.x, tid = threadIdx.x;

    if (bid < PEU_BLOCKS) {
        pe_block(user_emb, w1, 0, g_pe_user, NU, bid * 256, W1h, E, tid);
    } else if (bid < PEU_BLOCKS + PEI_BLOCKS) {
        pe_block(item_emb, w1, 64, g_pe_item, NI, (bid - PEU_BLOCKS) * 256, W1h, E, tid);
    } else if (bid < PEU_BLOCKS + PEI_BLOCKS + SCRU_BLOCKS) {
        int base = (bid - PEU_BLOCKS - PEI_BLOCKS) * SCR_CPB;
        for (int i = tid; i < SCR_CPB; i += 256)
            scr_chunk(user_scr, g_uscr16, NU, base + i);
    } else if (bid < PEU_BLOCKS + PEI_BLOCKS + SCRU_BLOCKS + SCRI_BLOCKS) {
        int base = (bid - PEU_BLOCKS - PEI_BLOCKS - SCRU_BLOCKS) * SCR_CPB;
        for (int i = tid; i < SCR_CPB; i += 256)
            scr_chunk(item_scr, g_iscr16, NI, base + i);
    } else {
        for (int t = tid; t < 7296; t += 256) {
            if (t < 4096) g_w2h[t] = __float2half_rn(w2[t]);
            else if (t < 6144) g_w3h[t - 4096] = __float2half_rn(w3[t - 4096]);
            else if (t < 7168) g_w4h[t - 6144] = __float2half_rn(w4[t - 6144]);
            else if (t < 7232) g_b2h[t - 7168] = __float2half_rn(b2[t - 7168]);
            else if (t < 7264) g_b3h[t - 7232] = __float2half_rn(b3[t - 7232]);
            else g_b4h[t - 7264] = __float2half_rn(b4[t - 7264]);
        }
    }
}

// ---------------------------------------------------------------------------
__global__ __launch_bounds__(256, 3) void cnn_main_kernel(
    const float* __restrict__ b1g,
    const float* __restrict__ w5g, const float* __restrict__ b5g,
    const int* __restrict__ uidxT, const int* __restrict__ iidxT,
    const int* __restrict__ uidxs, const int* __restrict__ iidxs,
    float* __restrict__ out)
{
    extern __shared__ char smb[];
    float* misc = (float*)(smb + OFF_MISC);
    int* nidx = (int*)(misc + MISC_NIDX);
    uint32_t sbase = (uint32_t)__cvta_generic_to_shared(smb);
    const int tid = threadIdx.x;
    const int b = blockIdx.x;

    // Phase 0: neighbor indices, w5/b5, zero B1 pad rows (k 100-111, 212-223)
    if (tid < 200) {
        nidx[tid] = (tid < 100) ? uidxT[(size_t)uidxs[b] * KN + tid]
                                : iidxT[(size_t)iidxs[b] * KN + (tid - 100)];
    } else if (tid < 232) {
        misc[MISC_W5 + tid - 200] = w5g[tid - 200];
    } else if (tid == 232) {
        misc[MISC_B5] = b5g[0];
    }
    if (tid < 192) {
        int rr = tid >> 3;
        int row = (rr < 12) ? 100 + rr : 200 + rr;
        *(uint4*)(smb + OFF_B1 + row * 128 + (tid & 7) * 16) = make_uint4(0, 0, 0, 0);
    }
    __syncthreads();

    // Phase 1: gathers via cp.async
    // ABUF pass-1: user scr halves, rows 0-99 x 14 chunks
    for (int t = tid; t < 1400; t += 256) {
        int r = t / 14, c = t % 14;
        CP_ASYNC16(sbase + OFF_AB + (uint32_t)(r * 240 + c * 16),
                   (const char*)(g_uscr16 + (size_t)nidx[r] * 112) + c * 16);
    }
    // B1: k-major pe rows, swizzled chunks; j<100 -> rows 0-99, j>=100 -> rows 112-211
    for (int t = tid; t < 1600; t += 256) {
        int j = t >> 3, c = t & 7;
        const char* src = (j < 100)
            ? (const char*)(g_pe_user + (size_t)nidx[j] * 64) + c * 16
            : (const char*)(g_pe_item + (size_t)nidx[j] * 64) + c * 16;
        int dr = (j < 100) ? j : j + 12;
        CP_ASYNC16(sbase + OFF_B1 + (uint32_t)(dr * 128 + ((c ^ (dr & 7)) << 4)), src);
    }
    for (int t = tid; t < 512; t += 256) {
        int o = t >> 3, c = t & 7;
        CP_ASYNC16(sbase + OFF_W2 + (uint32_t)(o * 144 + c * 16),
                   (const char*)(g_w2h + o * 64 + c * 8));
    }
    if (tid < 256) {
        int o = tid >> 3, c = tid & 7;
        CP_ASYNC16(sbase + OFF_W3 + (uint32_t)(o * 144 + c * 16),
                   (const char*)(g_w3h + o * 64 + c * 8));
    }
    if (tid < 128) {
        int o = tid >> 2, c = tid & 3;
        CP_ASYNC16(sbase + OFF_W4 + (uint32_t)(o * 80 + c * 16),
                   (const char*)(g_w4h + o * 32 + c * 8));
    }
    CP_COMMIT();
    CP_WAIT0();
    __syncthreads();   // block sync #1: all tiles resident

    const int lane = tid & 31, w = tid >> 5;
    const int mw = w >> 1, nw = w & 1;
    const int mtn = (mw == 3) ? 1 : 2;
    const int cc = (lane & 3) * 2;
    const int r = lane >> 2;
    const int pbar = mw + 1;                 // named barrier per pair
    const int wtid = tid & 63;               // thread id within pair
    const int pairA = OFF_AB + mw * 7680;    // pair slice of ABUF (own 32 rows)
    const int pairB = OFF_B1 + mw * 7168;    // pair slice of B1 (post-GEMM1 scratch)

    // ---- GEMM1 (fp32 acc): rows mw*32.., cols nw*32.., K=224 in 2 passes of 7
    {
        float2 bfrag[4];
#pragma unroll
        for (int nt = 0; nt < 4; nt++)
            bfrag[nt] = *(const float2*)(b1g + nw * 32 + nt * 8 + cc);

        uint32_t aAddr[2];
#pragma unroll
        for (int mt = 0; mt < 2; mt++)
            aAddr[mt] = sbase + OFF_AB
                      + (uint32_t)(mw * 32 + mt * 16 + (lane & 15)) * 240u
                      + (uint32_t)((lane >> 4) << 4);
        // swizzle folds to a per-lane constant: row&7 == lane&7 for all k-steps
        uint32_t bAddr[4];
#pragma unroll
        for (int nt = 0; nt < 4; nt++)
            bAddr[nt] = sbase + OFF_B1 + (uint32_t)(lane & 15) * 128u
                      + (uint32_t)((((nw * 4 + nt) ^ (lane & 7)) & 7) << 4);

        float acc[2][4][4];
#pragma unroll
        for (int mt = 0; mt < 2; mt++)
#pragma unroll
            for (int nt = 0; nt < 4; nt++)
#pragma unroll
                for (int i = 0; i < 4; i++) acc[mt][nt][i] = 0.f;

        // pass 1: user half (B1 rows 0-111)
#pragma unroll
        for (int ks = 0; ks < 7; ks++) {
            uint32_t bq[4][2];
#pragma unroll
            for (int nt = 0; nt < 4; nt++) ldsm2t(bq[nt], bAddr[nt] + ks * 2048);
#pragma unroll
            for (int mt = 0; mt < 2; mt++) {
                if (mt < mtn) {
                    uint32_t a[4];
                    ldsm4(a, aAddr[mt] + ks * 32);
#pragma unroll
                    for (int nt = 0; nt < 4; nt++) mma_f32acc(acc[mt][nt], a, bq[nt]);
                }
            }
        }

        // pair-local ABUF reload: item half into own 32 rows
        BAR64(pbar);   // both warps of pair done reading ABUF pass-1
        for (int t = wtid; t < 448; t += 64) {
            int rl = t / 14, c = t % 14;
            int rr = mw * 32 + rl;
            if (rr < 100)
                CP_ASYNC16(sbase + OFF_AB + (uint32_t)(rr * 240 + c * 16),
                           (const char*)(g_iscr16 + (size_t)nidx[100 + rr] * 112) + c * 16);
        }
        CP_COMMIT();
        CP_WAIT0();
        BAR64(pbar);   // pair's item half resident

        // pass 2: item half (B1 rows 112-223)
#pragma unroll
        for (int ks = 0; ks < 7; ks++) {
            uint32_t bq[4][2];
#pragma unroll
            for (int nt = 0; nt < 4; nt++) ldsm2t(bq[nt], bAddr[nt] + 14336 + ks * 2048);
#pragma unroll
            for (int mt = 0; mt < 2; mt++) {
                if (mt < mtn) {
                    uint32_t a[4];
                    ldsm4(a, aAddr[mt] + ks * 32);
#pragma unroll
                    for (int nt = 0; nt < 4; nt++) mma_f32acc(acc[mt][nt], a, bq[nt]);
                }
            }
        }
        __syncthreads();   // block: all pairs done reading B1 before H1 overwrites it

#pragma unroll
        for (int mt = 0; mt < 2; mt++) {
            if (mt < mtn) {
                int lrow = mt * 16 + r;
#pragma unroll
                for (int nt = 0; nt < 4; nt++) {
                    int col = nw * 32 + nt * 8 + cc;
                    *(uint32_t*)(smb + pairB + lrow * 144 + col * 2) =
                        h2_bits(fmaxf(acc[mt][nt][0] + bfrag[nt].x, 0.f),
                                fmaxf(acc[mt][nt][1] + bfrag[nt].y, 0.f));
                    *(uint32_t*)(smb + pairB + (lrow + 8) * 144 + col * 2) =
                        h2_bits(fmaxf(acc[mt][nt][2] + bfrag[nt].x, 0.f),
                                fmaxf(acc[mt][nt][3] + bfrag[nt].y, 0.f));
                }
            }
        }
    }
    BAR64(pbar);   // pair: H1 complete

    // ---- L2 (f16 acc): K=64, N=64; H1 (pairB) -> H2 (pairA)
    {
        __half2 bias2[4];
#pragma unroll
        for (int nt = 0; nt < 4; nt++)
            bias2[nt] = *(const __half2*)(g_b2h + nw * 32 + nt * 8 + cc);

        uint32_t aA = sbase + pairB + (uint32_t)(lane & 15) * 144u
                    + (uint32_t)((lane >> 4) << 4);
        uint32_t bAddr[4];
#pragma unroll
        for (int nt = 0; nt < 4; nt++)
            bAddr[nt] = sbase + OFF_W2 + (uint32_t)(nw * 32 + nt * 8 + (lane & 7)) * 144u
                      + (uint32_t)(((lane >> 3) & 1) << 4);

        uint32_t acc[2][4][2];
#pragma unroll
        for (int mt = 0; mt < 2; mt++)
#pragma unroll
            for (int nt = 0; nt < 4; nt++) { acc[mt][nt][0] = 0u; acc[mt][nt][1] = 0u; }

#pragma unroll
        for (int ks = 0; ks < 4; ks++) {
            uint32_t bq[4][2];
#pragma unroll
            for (int nt = 0; nt < 4; nt++) ldsm2(bq[nt], bAddr[nt] + ks * 32);
#pragma unroll
            for (int mt = 0; mt < 2; mt++) {
                if (mt < mtn) {
                    uint32_t a[4];
                    ldsm4(a, aA + mt * 2304 + ks * 32);
#pragma unroll
                    for (int nt = 0; nt < 4; nt++) mma_f16acc(acc[mt][nt], a, bq[nt]);
                }
            }
        }

        const __half2 z = __floats2half2_rn(0.f, 0.f);
#pragma unroll
        for (int mt = 0; mt < 2; mt++) {
            if (mt < mtn) {
                int lrow = mt * 16 + r;
#pragma unroll
                for (int nt = 0; nt < 4; nt++) {
                    int col = nw * 32 + nt * 8 + cc;
                    __half2 v0 = __hmax2(__hadd2(*(__half2*)&acc[mt][nt][0], bias2[nt]), z);
                    __half2 v1 = __hmax2(__hadd2(*(__half2*)&acc[mt][nt][1], bias2[nt]), z);
                    *(uint32_t*)(smb + pairA + lrow * 144 + col * 2) = *(uint32_t*)&v0;
                    *(uint32_t*)(smb + pairA + (lrow + 8) * 144 + col * 2) = *(uint32_t*)&v1;
                }
            }
        }
    }
    BAR64(pbar);   // pair: H2 complete

    // ---- L3 (f16 acc): K=64, N=32; H2 (pairA) -> H3 (pairB+4608, stride 80)
    {
        __half2 bias2[2];
#pragma unroll
        for (int nt = 0; nt < 2; nt++)
            bias2[nt] = *(const __half2*)(g_b3h + nw * 16 + nt * 8 + cc);

        uint32_t aA = sbase + pairA + (uint32_t)(lane & 15) * 144u
                    + (uint32_t)((lane >> 4) << 4);
        uint32_t bAddr[2];
#pragma unroll
        for (int nt = 0; nt < 2; nt++)
            bAddr[nt] = sbase + OFF_W3 + (uint32_t)(nw * 16 + nt * 8 + (lane & 7)) * 144u
                      + (uint32_t)(((lane >> 3) & 1) << 4);

        uint32_t acc[2][2][2];
#pragma unroll
        for (int mt = 0; mt < 2; mt++)
#pragma unroll
            for (int nt = 0; nt < 2; nt++) { acc[mt][nt][0] = 0u; acc[mt][nt][1] = 0u; }

#pragma unroll
        for (int ks = 0; ks < 4; ks++) {
            uint32_t bq[2][2];
#pragma unroll
            for (int nt = 0; nt < 2; nt++) ldsm2(bq[nt], bAddr[nt] + ks * 32);
#pragma unroll
            for (int mt = 0; mt < 2; mt++) {
                if (mt < mtn) {
                    uint32_t a[4];
                    ldsm4(a, aA + mt * 2304 + ks * 32);
#pragma unroll
                    for (int nt = 0; nt < 2; nt++) mma_f16acc(acc[mt][nt], a, bq[nt]);
                }
            }
        }

        const __half2 z = __floats2half2_rn(0.f, 0.f);
#pragma unroll
        for (int mt = 0; mt < 2; mt++) {
            if (mt < mtn) {
                int lrow = mt * 16 + r;
#pragma unroll
                for (int nt = 0; nt < 2; nt++) {
                    int col = nw * 16 + nt * 8 + cc;
                    __half2 v0 = __hmax2(__hadd2(*(__half2*)&acc[mt][nt][0], bias2[nt]), z);
                    __half2 v1 = __hmax2(__hadd2(*(__half2*)&acc[mt][nt][1], bias2[nt]), z);
                    *(uint32_t*)(smb + pairB + 4608 + lrow * 80 + col * 2) = *(uint32_t*)&v0;
                    *(uint32_t*)(smb + pairB + 4608 + (lrow + 8) * 80 + col * 2) = *(uint32_t*)&v1;
                }
            }
        }
    }
    BAR64(pbar);   // pair: H3 complete

    // ---- L4 (f16 acc, K=32, N=32) in registers + L5 dot with w5 ----
    {
        __half2 bias2[2];
        float w5f[2][2];
#pragma unroll
        for (int nt = 0; nt < 2; nt++) {
            int col = nw * 16 + nt * 8 + cc;
            bias2[nt] = *(const __half2*)(g_b4h + col);
            w5f[nt][0] = misc[MISC_W5 + col];
            w5f[nt][1] = misc[MISC_W5 + col + 1];
        }

        uint32_t aA = sbase + pairB + 4608 + (uint32_t)(lane & 15) * 80u
                    + (uint32_t)((lane >> 4) << 4);
        uint32_t bAddr[2];
#pragma unroll
        for (int nt = 0; nt < 2; nt++)
            bAddr[nt] = sbase + OFF_W4 + (uint32_t)(nw * 16 + nt * 8 + (lane & 7)) * 80u
                      + (uint32_t)(((lane >> 3) & 1) << 4);

        uint32_t acc[2][2][2];
#pragma unroll
        for (int mt = 0; mt < 2; mt++)
#pragma unroll
            for (int nt = 0; nt < 2; nt++) { acc[mt][nt][0] = 0u; acc[mt][nt][1] = 0u; }

#pragma unroll
        for (int ks = 0; ks < 2; ks++) {
            uint32_t bq[2][2];
#pragma unroll
            for (int nt = 0; nt < 2; nt++) ldsm2(bq[nt], bAddr[nt] + ks * 32);
#pragma unroll
            for (int mt = 0; mt < 2; mt++) {
                if (mt < mtn) {
                    uint32_t a[4];
                    ldsm4(a, aA + mt * 1280 + ks * 32);
#pragma unroll
                    for (int nt = 0; nt < 2; nt++) mma_f16acc(acc[mt][nt], a, bq[nt]);
                }
            }
        }

        const __half2 z = __floats2half2_rn(0.f, 0.f);
        float* RED = misc + (nw ? MISC_RED1 : MISC_RED0);
#pragma unroll
        for (int mt = 0; mt < 2; mt++) {
            if (mt < mtn) {
                float s0 = 0.f, s1 = 0.f;
#pragma unroll
                for (int nt = 0; nt < 2; nt++) {
                    __half2 h0 = __hmax2(__hadd2(*(__half2*)&acc[mt][nt][0], bias2[nt]), z);
                    __half2 h1 = __hmax2(__hadd2(*(__half2*)&acc[mt][nt][1], bias2[nt]), z);
                    float2 f0 = __half22float2(h0);
                    float2 f1 = __half22float2(h1);
                    s0 += f0.x * w5f[nt][0] + f0.y * w5f[nt][1];
                    s1 += f1.x * w5f[nt][0] + f1.y * w5f[nt][1];
                }
                s0 += __shfl_xor_sync(0xffffffffu, s0, 1);
                s0 += __shfl_xor_sync(0xffffffffu, s0, 2);
                s1 += __shfl_xor_sync(0xffffffffu, s1, 1);
                s1 += __shfl_xor_sync(0xffffffffu, s1, 2);
                if ((lane & 3) == 0) {
                    int row = mw * 32 + mt * 16 + r;
                    RED[row] = s0;
                    RED[row + 8] = s1;
                }
            }
        }
    }
    __syncthreads();   // block sync: all RED partials done

    // L5: sigmoid(s + b5), then mean over rows 0-99
    if (tid < 100) {
        float s = misc[MISC_RED0 + tid] + misc[MISC_RED1 + tid] + misc[MISC_B5];
        misc[MISC_RED0 + tid] = 1.f / (1.f + __expf(-s));
    }
    __syncthreads();
    if (tid < 32) {
        float v = misc[MISC_RED0 + tid] + misc[MISC_RED0 + tid + 32]
                + misc[MISC_RED0 + tid + 64]
                + ((tid < 4) ? misc[MISC_RED0 + tid + 96] : 0.f);
#pragma unroll
        for (int off = 16; off; off >>= 1)
            v += __shfl_down_sync(0xffffffffu, v, off);
        if (tid == 0) out[b] = v * (1.f / 100.f);
    }
}

// ---------------------------------------------------------------------------
extern "C" void kernel_launch(void* const* d_in, const int* in_sizes, int n_in,
                              void* d_out, int out_size)
{
    const float* user_emb = (const float*)d_in[0];
    const float* item_emb = (const float*)d_in[1];
    const float* user_scr = (const float*)d_in[2];
    const float* item_scr = (const float*)d_in[3];
    const float* w1 = (const float*)d_in[4];
    const float* b1 = (const float*)d_in[5];
    const float* w2 = (const float*)d_in[6];
    const float* b2 = (const float*)d_in[7];
    const float* w3 = (const float*)d_in[8];
    const float* b3 = (const float*)d_in[9];
    const float* w4 = (const float*)d_in[10];
    const float* b4 = (const float*)d_in[11];
    const float* w5 = (const float*)d_in[12];
    const float* b5 = (const float*)d_in[13];
    const int* user_idx_tensor = (const int*)d_in[14];
    const int* item_idx_tensor = (const int*)d_in[15];
    const int* user_idxs = (const int*)d_in[16];
    const int* item_idxs = (const int*)d_in[17];
    float* out = (float*)d_out;

    pre_kernel<<<PRE_BLOCKS, 256>>>(user_emb, item_emb, user_scr, item_scr,
                                    w1, w2, w3, w4, b2, b3, b4);

    cudaFuncSetAttribute(cnn_main_kernel,
                         cudaFuncAttributeMaxDynamicSharedMemorySize, SMEM_BYTES);
    cnn_main_kernel<<<BB, 256, SMEM_BYTES>>>(
        b1, w5, b5,
        user_idx_tensor, item_idx_tensor, user_idxs, item_idxs,
        out);
}